// round 1
// baseline (speedup 1.0000x reference)
#include <cuda_runtime.h>
#include <math.h>

#define S_LEN 1024
#define B_DIM 64
#define NBLK  128

// ---------------- device scratch (static: no allocs allowed) ----------------
__device__ float g_pre[S_LEN * B_DIM * 1536];   // xz|xr|xh preactivations (384MB)
__device__ float g_WT[512 * 1536];              // [k][n]  n: z|r|h input weights
__device__ float g_UTzr[512 * 1024];            // [k][n]  n: z|r recurrent weights
__device__ float g_UTh[512 * 512];              // [k][n]  h recurrent weights
__device__ float g_wbias[1536];
__device__ float g_ubias[1536];
__device__ float g_p1[8 * B_DIM * 1024];        // phase-1 k-split partials
__device__ float g_p2[16 * B_DIM * 512];        // phase-2 k-split partials
__device__ float g_z[B_DIM * 512];
__device__ float g_rh[B_DIM * 512];
__device__ unsigned g_bar_count;
__device__ unsigned g_bar_gen;

// ---------------- pack: transpose weights to k-major, concat biases ---------
__global__ void pack_kernel(const float* Wz, const float* bz, const float* Uz, const float* ubz,
                            const float* Wr, const float* br, const float* Ur, const float* ubr,
                            const float* Wh, const float* bh, const float* Uh, const float* ubh) {
    int stride = gridDim.x * blockDim.x;
    int t = blockIdx.x * blockDim.x + threadIdx.x;
    for (int idx = t; idx < 512 * 1536; idx += stride) {
        int k = idx / 1536, n = idx % 1536;
        const float* W = (n < 512) ? Wz : (n < 1024 ? Wr : Wh);
        g_WT[idx] = W[(n & 511) * 512 + k];
    }
    for (int idx = t; idx < 512 * 1024; idx += stride) {
        int k = idx >> 10, n = idx & 1023;
        const float* U = (n < 512) ? Uz : Ur;
        g_UTzr[idx] = U[(n & 511) * 512 + k];
    }
    for (int idx = t; idx < 512 * 512; idx += stride) {
        int k = idx >> 9, n = idx & 511;
        g_UTh[idx] = Uh[n * 512 + k];
    }
    for (int idx = t; idx < 1536; idx += stride) {
        int n = idx & 511;
        g_wbias[idx] = (idx < 512) ? bz[n] : (idx < 1024 ? br[n] : bh[n]);
        g_ubias[idx] = (idx < 512) ? ubz[n] : (idx < 1024 ? ubr[n] : ubh[n]);
    }
}

// ---------------- input projection GEMM: pre = x @ WT + wbias ---------------
// C[65536, 1536] = X[65536, 512] * WT[512, 1536]
// Tile: BM=128, BN=64, BK=16; 256 threads; per-thread 8x4.
__global__ __launch_bounds__(256) void input_gemm(const float* __restrict__ x) {
    __shared__ float As[16 * 132];   // [k][m], padded pitch
    __shared__ float Bs[16 * 64];    // [k][n]
    int tid = threadIdx.x;
    int tx = tid & 15, ty = tid >> 4;
    int m0 = blockIdx.y * 128;
    int n0 = blockIdx.x * 64;

    float acc[8][4];
#pragma unroll
    for (int i = 0; i < 8; i++)
#pragma unroll
        for (int j = 0; j < 4; j++) acc[i][j] = 0.f;

    for (int kt = 0; kt < 32; kt++) {
        int k0 = kt * 16;
        // load A tile (128x16), transpose into As[k][m]
#pragma unroll
        for (int i = 0; i < 2; i++) {
            int f = i * 256 + tid;          // 0..511
            int m = f >> 2, kq = f & 3;
            float4 v = *(const float4*)(x + (m0 + m) * 512 + k0 + kq * 4);
            As[(kq * 4 + 0) * 132 + m] = v.x;
            As[(kq * 4 + 1) * 132 + m] = v.y;
            As[(kq * 4 + 2) * 132 + m] = v.z;
            As[(kq * 4 + 3) * 132 + m] = v.w;
        }
        // load B tile (16x64)
        {
            int k = tid >> 4, nq = tid & 15;
            *(float4*)&Bs[k * 64 + nq * 4] =
                *(const float4*)(g_WT + (k0 + k) * 1536 + n0 + nq * 4);
        }
        __syncthreads();
#pragma unroll
        for (int kk = 0; kk < 16; kk++) {
            float ar[8], br[4];
            *(float4*)&ar[0] = *(const float4*)&As[kk * 132 + ty * 8];
            *(float4*)&ar[4] = *(const float4*)&As[kk * 132 + ty * 8 + 4];
            *(float4*)&br[0] = *(const float4*)&Bs[kk * 64 + tx * 4];
#pragma unroll
            for (int i = 0; i < 8; i++)
#pragma unroll
                for (int j = 0; j < 4; j++) acc[i][j] += ar[i] * br[j];
        }
        __syncthreads();
    }
    // epilogue: add input bias, store
#pragma unroll
    for (int i = 0; i < 8; i++) {
        int m = m0 + ty * 8 + i;
        int n = n0 + tx * 4;
        float4 o;
        o.x = acc[i][0] + g_wbias[n + 0];
        o.y = acc[i][1] + g_wbias[n + 1];
        o.z = acc[i][2] + g_wbias[n + 2];
        o.w = acc[i][3] + g_wbias[n + 3];
        *(float4*)&g_pre[m * 1536 + n] = o;
    }
}

// ---------------- grid-wide barrier (persistent kernel) ---------------------
__device__ __forceinline__ void grid_sync() {
    __syncthreads();
    if (threadIdx.x == 0) {
        __threadfence();
        unsigned gen = *((volatile unsigned*)&g_bar_gen);
        if (atomicAdd(&g_bar_count, 1u) == NBLK - 1) {
            g_bar_count = 0;
            __threadfence();
            *((volatile unsigned*)&g_bar_gen) = gen + 1;
        } else {
            while (*((volatile unsigned*)&g_bar_gen) == gen) { }
            __threadfence();
        }
    }
    __syncthreads();
}

// ---------------- persistent GRU scan ---------------------------------------
// grid = 128 CTAs x 256 threads, all co-resident.
// Per step:
//   P1: partials of h @ [Uz|Ur]^T  (16 n-tiles of 64) x (8 k-splits of 64)
//   F1: z = sigmoid(...), rh = sigmoid(...)*h
//   P2: partials of rh @ Uh^T      (8 n-tiles of 64) x (16 k-splits of 32)
//   F2: h_new = h + z*(tanh(...) - h) -> out[s]
__global__ __launch_bounds__(256, 1) void gru_scan(const float* __restrict__ h0,
                                                   float* out) {
    __shared__ float sh[64 * 65 + 64 * 64];   // 33,280 B

    const int tid = threadIdx.x;
    const int cta = blockIdx.x;
    const int tn0 = (tid & 15) * 4;   // thread n-offset (4 cols)
    const int tb0 = (tid >> 4) * 4;   // thread b-offset (4 rows)

    for (int s = 0; s < S_LEN; s++) {
        const float* hprev = (s == 0) ? h0 : (out + (s - 1) * (B_DIM * 512));

        // ---------------- P1 compute ----------------
        {
            const int nt = cta >> 3;         // 0..15
            const int ks = cta & 7;          // 0..7
            const int nbase = nt * 64, kbase = ks * 64;
            float* hs = sh;                  // [64][65]
            float* us = sh + 64 * 65;        // [64][64]
#pragma unroll
            for (int i = 0; i < 4; i++) {    // h tile: 64b x 64k
                int f = i * 256 + tid;       // 0..1023
                int b = f >> 4, kq = f & 15;
                float4 v = *(const float4*)(hprev + b * 512 + kbase + kq * 4);
                hs[b * 65 + kq * 4 + 0] = v.x;
                hs[b * 65 + kq * 4 + 1] = v.y;
                hs[b * 65 + kq * 4 + 2] = v.z;
                hs[b * 65 + kq * 4 + 3] = v.w;
            }
#pragma unroll
            for (int i = 0; i < 4; i++) {    // U tile: 64k x 64n
                int f = i * 256 + tid;
                int k = f >> 4, nq = f & 15;
                *(float4*)&us[k * 64 + nq * 4] =
                    *(const float4*)(g_UTzr + (kbase + k) * 1024 + nbase + nq * 4);
            }
            __syncthreads();
            float acc[4][4];
#pragma unroll
            for (int i = 0; i < 4; i++)
#pragma unroll
                for (int j = 0; j < 4; j++) acc[i][j] = 0.f;
#pragma unroll 8
            for (int kk = 0; kk < 64; kk++) {
                float ur[4], hr[4];
                *(float4*)ur = *(const float4*)&us[kk * 64 + tn0];
#pragma unroll
                for (int i = 0; i < 4; i++) hr[i] = hs[(tb0 + i) * 65 + kk];
#pragma unroll
                for (int i = 0; i < 4; i++)
#pragma unroll
                    for (int j = 0; j < 4; j++) acc[i][j] += hr[i] * ur[j];
            }
#pragma unroll
            for (int i = 0; i < 4; i++) {
                float4 o = make_float4(acc[i][0], acc[i][1], acc[i][2], acc[i][3]);
                *(float4*)&g_p1[(ks * 64 + tb0 + i) * 1024 + nbase + tn0] = o;
            }
        }
        grid_sync();

        // ---------------- F1: sigmoid, z and r*h ----------------
        {
            int base = (cta * 256 + tid) * 2;
#pragma unroll
            for (int q = 0; q < 2; q++) {
                int e = base + q;            // [0, 65536): first half z, second r
                int b = (e >> 9) & 63;
                int j = e & 511;
                int isr = e >> 15;
                int n = isr ? (512 + j) : j;
                float ssum = 0.f;
#pragma unroll
                for (int p = 0; p < 8; p++) ssum += g_p1[(p * 64 + b) * 1024 + n];
                float a = g_pre[(s * 64 + b) * 1536 + n] + ssum + g_ubias[n];
                float v = 1.f / (1.f + expf(-a));
                if (isr) g_rh[b * 512 + j] = v * hprev[b * 512 + j];
                else     g_z[b * 512 + j] = v;
            }
        }
        grid_sync();

        // ---------------- P2 compute ----------------
        {
            const int nt = cta >> 4;          // 0..7
            const int ks = cta & 15;          // 0..15
            const int nbase = nt * 64, kbase = ks * 32;
            float* rhs = sh;                  // [64][33]
            float* us2 = sh + 64 * 33;        // [32][64]
#pragma unroll
            for (int i = 0; i < 2; i++) {     // rh tile: 64b x 32k
                int f = i * 256 + tid;        // 0..511
                int b = f >> 3, kq = f & 7;
                float4 v = *(const float4*)(g_rh + b * 512 + kbase + kq * 4);
                rhs[b * 33 + kq * 4 + 0] = v.x;
                rhs[b * 33 + kq * 4 + 1] = v.y;
                rhs[b * 33 + kq * 4 + 2] = v.z;
                rhs[b * 33 + kq * 4 + 3] = v.w;
            }
#pragma unroll
            for (int i = 0; i < 2; i++) {     // Uh tile: 32k x 64n
                int f = i * 256 + tid;
                int k = f >> 4, nq = f & 15;
                *(float4*)&us2[k * 64 + nq * 4] =
                    *(const float4*)(g_UTh + (kbase + k) * 512 + nbase + nq * 4);
            }
            __syncthreads();
            float acc[4][4];
#pragma unroll
            for (int i = 0; i < 4; i++)
#pragma unroll
                for (int j = 0; j < 4; j++) acc[i][j] = 0.f;
#pragma unroll 8
            for (int kk = 0; kk < 32; kk++) {
                float ur[4], hr[4];
                *(float4*)ur = *(const float4*)&us2[kk * 64 + tn0];
#pragma unroll
                for (int i = 0; i < 4; i++) hr[i] = rhs[(tb0 + i) * 33 + kk];
#pragma unroll
                for (int i = 0; i < 4; i++)
#pragma unroll
                    for (int j = 0; j < 4; j++) acc[i][j] += hr[i] * ur[j];
            }
#pragma unroll
            for (int i = 0; i < 4; i++) {
                float4 o = make_float4(acc[i][0], acc[i][1], acc[i][2], acc[i][3]);
                *(float4*)&g_p2[(ks * 64 + tb0 + i) * 512 + nbase + tn0] = o;
            }
        }
        grid_sync();

        // ---------------- F2: tanh, gate update, write output ----------------
        {
            int e = cta * 256 + tid;          // [0, 32768)
            int b = e >> 9, j = e & 511;
            float ssum = 0.f;
#pragma unroll
            for (int p = 0; p < 16; p++) ssum += g_p2[(p * 64 + b) * 512 + j];
            float a = g_pre[(s * 64 + b) * 1536 + 1024 + j] + ssum + g_ubias[1024 + j];
            float ht = tanhf(a);
            float z = g_z[e];
            float hp = hprev[e];
            float hn = hp + z * (ht - hp);
            out[s * (B_DIM * 512) + e] = hn;
            if (s == S_LEN - 1) out[S_LEN * (B_DIM * 512) + e] = hn;   // hx
        }
        grid_sync();
    }
}

// ---------------- launch ----------------------------------------------------
extern "C" void kernel_launch(void* const* d_in, const int* in_sizes, int n_in,
                              void* d_out, int out_size) {
    (void)in_sizes; (void)n_in; (void)out_size;
    const float* x    = (const float*)d_in[0];
    const float* h0   = (const float*)d_in[1];
    const float* Wz_w = (const float*)d_in[2];
    const float* Wz_b = (const float*)d_in[3];
    const float* Uz_w = (const float*)d_in[4];
    const float* Uz_b = (const float*)d_in[5];
    const float* Wr_w = (const float*)d_in[6];
    const float* Wr_b = (const float*)d_in[7];
    const float* Ur_w = (const float*)d_in[8];
    const float* Ur_b = (const float*)d_in[9];
    const float* Wh_w = (const float*)d_in[10];
    const float* Wh_b = (const float*)d_in[11];
    const float* Uh_w = (const float*)d_in[12];
    const float* Uh_b = (const float*)d_in[13];
    float* out = (float*)d_out;

    pack_kernel<<<256, 256>>>(Wz_w, Wz_b, Uz_w, Uz_b,
                              Wr_w, Wr_b, Ur_w, Ur_b,
                              Wh_w, Wh_b, Uh_w, Uh_b);
    input_gemm<<<dim3(24, 512), 256>>>(x);
    gru_scan<<<NBLK, 256>>>(h0, out);
}

// round 2
// speedup vs baseline: 1.0299x; 1.0299x over previous
#include <cuda_runtime.h>
#include <math.h>

#define S_LEN 1024
#define B_DIM 64
#define NBLK  128

typedef unsigned long long u64;

// ---------------- f32x2 helpers (sm_100+) -----------------------------------
__device__ __forceinline__ u64 dupf(float x) {
    u64 r; unsigned xi = __float_as_uint(x);
    asm("mov.b64 %0, {%1, %1};" : "=l"(r) : "r"(xi));
    return r;
}
__device__ __forceinline__ void fma2(u64& d, u64 a, u64 b) {
    asm("fma.rn.f32x2 %0, %1, %2, %0;" : "+l"(d) : "l"(a), "l"(b));
}
__device__ __forceinline__ u64 add2(u64 a, u64 b) {
    u64 d; asm("add.rn.f32x2 %0, %1, %2;" : "=l"(d) : "l"(a), "l"(b));
    return d;
}
__device__ __forceinline__ void unpk(u64 p, float& lo, float& hi) {
    unsigned a, b;
    asm("mov.b64 {%0, %1}, %2;" : "=r"(a), "=r"(b) : "l"(p));
    lo = __uint_as_float(a); hi = __uint_as_float(b);
}

// ---------------- device scratch --------------------------------------------
__device__ float g_pre[S_LEN * B_DIM * 1536];   // xz|xr|xh preactivations
__device__ float g_WT[512 * 1536];              // [k][n] input weights (k-major)
__device__ float g_Uzrp[64 * 512 * 16];         // packed [nt][k][16n] zr weights
__device__ float g_Uhp[32 * 512 * 16];          // packed [nt][k][16n] h weights
__device__ float g_wbias[1536];
__device__ float g_ubias[1536];
__device__ float g_z[B_DIM * 512];
__device__ float g_rh[B_DIM * 512];
__device__ unsigned g_bar_count;
__device__ unsigned g_bar_gen;

// ---------------- pack ------------------------------------------------------
__global__ void pack_kernel(const float* Wz, const float* bz, const float* Uz, const float* ubz,
                            const float* Wr, const float* br, const float* Ur, const float* ubr,
                            const float* Wh, const float* bh, const float* Uh, const float* ubh) {
    int stride = gridDim.x * blockDim.x;
    int t = blockIdx.x * blockDim.x + threadIdx.x;
    for (int idx = t; idx < 512 * 1536; idx += stride) {
        int k = idx / 1536, n = idx % 1536;
        const float* W = (n < 512) ? Wz : (n < 1024 ? Wr : Wh);
        g_WT[idx] = W[(n & 511) * 512 + k];
    }
    for (int idx = t; idx < 64 * 512 * 16; idx += stride) {
        int nt = idx >> 13, k = (idx >> 4) & 511, nn = idx & 15;
        int n = nt * 16 + nn;
        g_Uzrp[idx] = (n < 512) ? Uz[n * 512 + k] : Ur[(n - 512) * 512 + k];
    }
    for (int idx = t; idx < 32 * 512 * 16; idx += stride) {
        int nt = idx >> 13, k = (idx >> 4) & 511, nn = idx & 15;
        g_Uhp[idx] = Uh[(nt * 16 + nn) * 512 + k];
    }
    for (int idx = t; idx < 1536; idx += stride) {
        int n = idx & 511;
        g_wbias[idx] = (idx < 512) ? bz[n] : (idx < 1024 ? br[n] : bh[n]);
        g_ubias[idx] = (idx < 512) ? ubz[n] : (idx < 1024 ? ubr[n] : ubh[n]);
    }
}

// ---------------- input projection GEMM (f32x2) -----------------------------
// C[65536,1536] = X[65536,512] * WT[512,1536];  BM=128,BN=64,BK=16, 8x4/thread
__global__ __launch_bounds__(256) void input_gemm(const float* __restrict__ x) {
    __shared__ float As[16 * 132];
    __shared__ float Bs[16 * 64];
    int tid = threadIdx.x;
    int tx = tid & 15, ty = tid >> 4;
    int m0 = blockIdx.y * 128;
    int n0 = blockIdx.x * 64;

    u64 acc[8][2];
#pragma unroll
    for (int i = 0; i < 8; i++) { acc[i][0] = 0ull; acc[i][1] = 0ull; }

    for (int kt = 0; kt < 32; kt++) {
        int k0 = kt * 16;
#pragma unroll
        for (int i = 0; i < 2; i++) {
            int f = i * 256 + tid;
            int m = f >> 2, kq = f & 3;
            float4 v = *(const float4*)(x + (m0 + m) * 512 + k0 + kq * 4);
            As[(kq * 4 + 0) * 132 + m] = v.x;
            As[(kq * 4 + 1) * 132 + m] = v.y;
            As[(kq * 4 + 2) * 132 + m] = v.z;
            As[(kq * 4 + 3) * 132 + m] = v.w;
        }
        {
            int k = tid >> 4, nq = tid & 15;
            *(float4*)&Bs[k * 64 + nq * 4] =
                *(const float4*)(g_WT + (k0 + k) * 1536 + n0 + nq * 4);
        }
        __syncthreads();
#pragma unroll
        for (int kk = 0; kk < 16; kk++) {
            float4 a0 = *(const float4*)&As[kk * 132 + ty * 8];
            float4 a1 = *(const float4*)&As[kk * 132 + ty * 8 + 4];
            ulonglong2 bb = *(const ulonglong2*)&Bs[kk * 64 + tx * 4];
            u64 d0 = dupf(a0.x), d1 = dupf(a0.y), d2 = dupf(a0.z), d3 = dupf(a0.w);
            u64 d4 = dupf(a1.x), d5 = dupf(a1.y), d6 = dupf(a1.z), d7 = dupf(a1.w);
            fma2(acc[0][0], d0, bb.x); fma2(acc[0][1], d0, bb.y);
            fma2(acc[1][0], d1, bb.x); fma2(acc[1][1], d1, bb.y);
            fma2(acc[2][0], d2, bb.x); fma2(acc[2][1], d2, bb.y);
            fma2(acc[3][0], d3, bb.x); fma2(acc[3][1], d3, bb.y);
            fma2(acc[4][0], d4, bb.x); fma2(acc[4][1], d4, bb.y);
            fma2(acc[5][0], d5, bb.x); fma2(acc[5][1], d5, bb.y);
            fma2(acc[6][0], d6, bb.x); fma2(acc[6][1], d6, bb.y);
            fma2(acc[7][0], d7, bb.x); fma2(acc[7][1], d7, bb.y);
        }
        __syncthreads();
    }
#pragma unroll
    for (int i = 0; i < 8; i++) {
        int m = m0 + ty * 8 + i;
        int n = n0 + tx * 4;
        float4 o;
        float v0, v1, v2, v3;
        unpk(acc[i][0], v0, v1);
        unpk(acc[i][1], v2, v3);
        o.x = v0 + g_wbias[n + 0];
        o.y = v1 + g_wbias[n + 1];
        o.z = v2 + g_wbias[n + 2];
        o.w = v3 + g_wbias[n + 3];
        *(float4*)&g_pre[m * 1536 + n] = o;
    }
}

// ---------------- grid-wide barrier -----------------------------------------
__device__ __forceinline__ void grid_sync() {
    __syncthreads();
    if (threadIdx.x == 0) {
        __threadfence();
        unsigned gen = *((volatile unsigned*)&g_bar_gen);
        if (atomicAdd(&g_bar_count, 1u) == NBLK - 1) {
            g_bar_count = 0;
            __threadfence();
            *((volatile unsigned*)&g_bar_gen) = gen + 1;
        } else {
            while (*((volatile unsigned*)&g_bar_gen) == gen) { }
            __threadfence();
        }
    }
    __syncthreads();
}

// ---------------- persistent GRU scan: 2 barriers/step ----------------------
// Phase1 (128 CTAs = 2 b-halves x 64 n-tiles of 16):
//   zr = sigmoid(pre_zr + h @ Uzr^T + ub) ; write z and rh = r*h
//   K=512 split across 8 warps (warp-private SMEM tiles), SMEM reduce.
// Phase2 (128 CTAs = 4 b-tiles of 16 x 32 n-tiles of 16):
//   h~ = tanh(pre_h + rh @ Uh^T + ub); h_new = h + z*(h~-h) -> out[s]
__global__ __launch_bounds__(256, 1) void gru_scan(const float* __restrict__ h0,
                                                   float* out) {
    extern __shared__ float smem[];
    // Phase 1 layout
    float* hT   = smem;                         // [512][36]   72KB
    float* us   = smem + 512 * 36;              // [512][16]   32KB
    u64*   red1 = (u64*)(us + 512 * 16);        // [8][256]    16KB
    // Phase 2 layout (reuse)
    float* rT   = smem;                         // [512][20]   40KB
    float* u2   = smem + 512 * 20;              // [512][16]   32KB
    u64*   red2 = (u64*)(u2 + 512 * 16);        // [8][128]     8KB

    const int tid  = threadIdx.x;
    const int cta  = blockIdx.x;
    const int w    = tid >> 5;
    const int lane = tid & 31;

    const int bt  = cta >> 6;    // phase1: b-half 0..1
    const int nt  = cta & 63;    // phase1: n-tile 0..63
    const int bt2 = cta >> 5;    // phase2: b-tile 0..3
    const int nt2 = cta & 31;    // phase2: n-tile 0..31

    for (int s = 0; s < S_LEN; s++) {
        const float* hprev = (s == 0) ? h0 : (out + (s - 1) * (B_DIM * 512));

        // ================= Phase 1 =================
        {
            // warp-private loads of this warp's k-slice [w*64, w*64+64)
            const int half = lane >> 4, l16 = lane & 15;
#pragma unroll
            for (int it = 0; it < 16; it++) {            // hT: 32b x 64k slice
                int b = it * 2 + half;
                int j = w * 64 + l16 * 4;
                float4 v = *(const float4*)(hprev + (bt * 32 + b) * 512 + j);
                hT[(j + 0) * 36 + b] = v.x;
                hT[(j + 1) * 36 + b] = v.y;
                hT[(j + 2) * 36 + b] = v.z;
                hT[(j + 3) * 36 + b] = v.w;
            }
            const float* up = g_Uzrp + nt * 8192;
#pragma unroll
            for (int it = 0; it < 8; it++) {             // us: 64k x 16n slice
                int off = w * 1024 + (it * 32 + lane) * 4;
                *(float4*)&us[off] = *(const float4*)(up + off);
            }
            // compute (warp-synchronous, own tiles only)
            const int bg = lane >> 2;        // b0 = bg*4
            const int ng = lane & 3;         // n0 = ng*4
            u64 acc[4][2];
#pragma unroll
            for (int i = 0; i < 4; i++) { acc[i][0] = 0ull; acc[i][1] = 0ull; }
#pragma unroll 16
            for (int kk = 0; kk < 64; kk++) {
                int k = w * 64 + kk;
                ulonglong2 uu = *(const ulonglong2*)(us + k * 16 + ng * 4);
                float4 hv = *(const float4*)(hT + k * 36 + bg * 4);
                u64 h0p = dupf(hv.x), h1p = dupf(hv.y), h2p = dupf(hv.z), h3p = dupf(hv.w);
                fma2(acc[0][0], h0p, uu.x); fma2(acc[0][1], h0p, uu.y);
                fma2(acc[1][0], h1p, uu.x); fma2(acc[1][1], h1p, uu.y);
                fma2(acc[2][0], h2p, uu.x); fma2(acc[2][1], h2p, uu.y);
                fma2(acc[3][0], h3p, uu.x); fma2(acc[3][1], h3p, uu.y);
            }
            // store partials to reduction buffer
            int rb = w * 256 + bg * 32 + ng * 2;
#pragma unroll
            for (int i = 0; i < 4; i++) {
                red1[rb + i * 8 + 0] = acc[i][0];
                red1[rb + i * 8 + 1] = acc[i][1];
            }
            __syncthreads();
            // reduce + sigmoid + scatter
            {
                int o = tid;                       // 256 ull outputs (32b x 8 pairs)
                u64 ssum = red1[o];
#pragma unroll
                for (int p = 1; p < 8; p++) ssum = add2(ssum, red1[p * 256 + o]);
                float s0, s1; unpk(ssum, s0, s1);
                int b_local = o >> 3, nl = (o & 7) * 2;
                int b = bt * 32 + b_local;
                int n = nt * 16 + nl;
                float a0 = g_pre[(s * 64 + b) * 1536 + n]     + s0 + g_ubias[n];
                float a1 = g_pre[(s * 64 + b) * 1536 + n + 1] + s1 + g_ubias[n + 1];
                float v0 = 1.f / (1.f + __expf(-a0));
                float v1 = 1.f / (1.f + __expf(-a1));
                if (nt < 32) {
                    g_z[b * 512 + n]     = v0;
                    g_z[b * 512 + n + 1] = v1;
                } else {
                    int j = n - 512;
                    g_rh[b * 512 + j]     = v0 * hT[j * 36 + b_local];
                    g_rh[b * 512 + j + 1] = v1 * hT[(j + 1) * 36 + b_local];
                }
            }
        }
        grid_sync();

        // ================= Phase 2 =================
        {
            const int half = lane >> 4, l16 = lane & 15;
#pragma unroll
            for (int it = 0; it < 8; it++) {             // rT: 16b x 64k slice
                int b = it * 2 + half;
                int j = w * 64 + l16 * 4;
                float4 v = *(const float4*)(g_rh + (bt2 * 16 + b) * 512 + j);
                rT[(j + 0) * 20 + b] = v.x;
                rT[(j + 1) * 20 + b] = v.y;
                rT[(j + 2) * 20 + b] = v.z;
                rT[(j + 3) * 20 + b] = v.w;
            }
            const float* up = g_Uhp + nt2 * 8192;
#pragma unroll
            for (int it = 0; it < 8; it++) {
                int off = w * 1024 + (it * 32 + lane) * 4;
                *(float4*)&u2[off] = *(const float4*)(up + off);
            }
            const int bg = lane >> 2;        // b0 = bg*2
            const int ng = lane & 3;         // n0 = ng*4
            u64 acc[2][2];
            acc[0][0] = acc[0][1] = acc[1][0] = acc[1][1] = 0ull;
#pragma unroll 16
            for (int kk = 0; kk < 64; kk++) {
                int k = w * 64 + kk;
                ulonglong2 uu = *(const ulonglong2*)(u2 + k * 16 + ng * 4);
                float2 rv = *(const float2*)(rT + k * 20 + bg * 2);
                u64 r0p = dupf(rv.x), r1p = dupf(rv.y);
                fma2(acc[0][0], r0p, uu.x); fma2(acc[0][1], r0p, uu.y);
                fma2(acc[1][0], r1p, uu.x); fma2(acc[1][1], r1p, uu.y);
            }
            int rb = w * 128 + bg * 16 + ng * 2;
            red2[rb + 0] = acc[0][0];
            red2[rb + 1] = acc[0][1];
            red2[rb + 8] = acc[1][0];
            red2[rb + 9] = acc[1][1];
            __syncthreads();
            if (tid < 128) {
                int o = tid;                       // 128 ull = 16b x 8 pairs
                u64 ssum = red2[o];
#pragma unroll
                for (int p = 1; p < 8; p++) ssum = add2(ssum, red2[p * 128 + o]);
                float s0, s1; unpk(ssum, s0, s1);
                int b_local = o >> 3, nl = (o & 7) * 2;
                int b = bt2 * 16 + b_local;
                int n = nt2 * 16 + nl;
#pragma unroll
                for (int c = 0; c < 2; c++) {
                    float sc = c ? s1 : s0;
                    int nc = n + c;
                    float a = g_pre[(s * 64 + b) * 1536 + 1024 + nc] + sc + g_ubias[1024 + nc];
                    float e = __expf(2.f * a);
                    float ht = 1.f - 2.f / (e + 1.f);
                    float z  = g_z[b * 512 + nc];
                    float hp = hprev[b * 512 + nc];
                    float hn = hp + z * (ht - hp);
                    out[s * (B_DIM * 512) + b * 512 + nc] = hn;
                    if (s == S_LEN - 1) out[S_LEN * (B_DIM * 512) + b * 512 + nc] = hn;
                }
            }
        }
        grid_sync();
    }
}

// ---------------- launch ----------------------------------------------------
extern "C" void kernel_launch(void* const* d_in, const int* in_sizes, int n_in,
                              void* d_out, int out_size) {
    (void)in_sizes; (void)n_in; (void)out_size;
    const float* x    = (const float*)d_in[0];
    const float* h0   = (const float*)d_in[1];
    const float* Wz_w = (const float*)d_in[2];
    const float* Wz_b = (const float*)d_in[3];
    const float* Uz_w = (const float*)d_in[4];
    const float* Uz_b = (const float*)d_in[5];
    const float* Wr_w = (const float*)d_in[6];
    const float* Wr_b = (const float*)d_in[7];
    const float* Ur_w = (const float*)d_in[8];
    const float* Ur_b = (const float*)d_in[9];
    const float* Wh_w = (const float*)d_in[10];
    const float* Wh_b = (const float*)d_in[11];
    const float* Uh_w = (const float*)d_in[12];
    const float* Uh_b = (const float*)d_in[13];
    float* out = (float*)d_out;

    static int smem_set = 0;
    if (!smem_set) {
        cudaFuncSetAttribute(gru_scan, cudaFuncAttributeMaxDynamicSharedMemorySize,
                             122880);
        smem_set = 1;
    }

    pack_kernel<<<256, 256>>>(Wz_w, Wz_b, Uz_w, Uz_b,
                              Wr_w, Wr_b, Ur_w, Ur_b,
                              Wh_w, Wh_b, Uh_w, Uh_b);
    input_gemm<<<dim3(24, 512), 256>>>(x);
    gru_scan<<<NBLK, 256, 122880>>>(h0, out);
}

// round 3
// speedup vs baseline: 1.2915x; 1.2539x over previous
#include <cuda_runtime.h>
#include <math.h>

#define S_LEN 1024
#define B_DIM 64
#define NBLK  128

typedef unsigned long long u64;

// ---------------- f32x2 helpers (sm_100+) -----------------------------------
__device__ __forceinline__ u64 dupf(float x) {
    u64 r; unsigned xi = __float_as_uint(x);
    asm("mov.b64 %0, {%1, %1};" : "=l"(r) : "r"(xi));
    return r;
}
__device__ __forceinline__ void fma2(u64& d, u64 a, u64 b) {
    asm("fma.rn.f32x2 %0, %1, %2, %0;" : "+l"(d) : "l"(a), "l"(b));
}
__device__ __forceinline__ u64 add2(u64 a, u64 b) {
    u64 d; asm("add.rn.f32x2 %0, %1, %2;" : "=l"(d) : "l"(a), "l"(b));
    return d;
}
__device__ __forceinline__ void unpk(u64 p, float& lo, float& hi) {
    unsigned a, b;
    asm("mov.b64 {%0, %1}, %2;" : "=r"(a), "=r"(b) : "l"(p));
    lo = __uint_as_float(a); hi = __uint_as_float(b);
}

// ---------------- device scratch --------------------------------------------
__device__ float g_pre[S_LEN * B_DIM * 1536];   // xz|xr|xh preactivations
__device__ float g_WT[512 * 1536];              // [k][n] input weights (k-major)
__device__ float g_Uzrp[64 * 512 * 16];         // packed [nt][k][16n] zr weights
__device__ float g_Uhp[32 * 512 * 16];          // packed [nt][k][16n] h weights
__device__ float g_wbias[1536];
__device__ float g_ubias[1536];
__device__ float g_z[B_DIM * 512];
__device__ float g_rh[B_DIM * 512];
__device__ unsigned g_flags[NBLK * 32];         // per-CTA barrier flags, 128B stride

// ---------------- pack + flag reset -----------------------------------------
__global__ void pack_kernel(const float* Wz, const float* bz, const float* Uz, const float* ubz,
                            const float* Wr, const float* br, const float* Ur, const float* ubr,
                            const float* Wh, const float* bh, const float* Uh, const float* ubh) {
    int stride = gridDim.x * blockDim.x;
    int t = blockIdx.x * blockDim.x + threadIdx.x;
    for (int idx = t; idx < NBLK * 32; idx += stride) g_flags[idx] = 0u;
    for (int idx = t; idx < 512 * 1536; idx += stride) {
        int k = idx / 1536, n = idx % 1536;
        const float* W = (n < 512) ? Wz : (n < 1024 ? Wr : Wh);
        g_WT[idx] = W[(n & 511) * 512 + k];
    }
    for (int idx = t; idx < 64 * 512 * 16; idx += stride) {
        int nt = idx >> 13, k = (idx >> 4) & 511, nn = idx & 15;
        int n = nt * 16 + nn;
        g_Uzrp[idx] = (n < 512) ? Uz[n * 512 + k] : Ur[(n - 512) * 512 + k];
    }
    for (int idx = t; idx < 32 * 512 * 16; idx += stride) {
        int nt = idx >> 13, k = (idx >> 4) & 511, nn = idx & 15;
        g_Uhp[idx] = Uh[(nt * 16 + nn) * 512 + k];
    }
    for (int idx = t; idx < 1536; idx += stride) {
        int n = idx & 511;
        g_wbias[idx] = (idx < 512) ? bz[n] : (idx < 1024 ? br[n] : bh[n]);
        g_ubias[idx] = (idx < 512) ? ubz[n] : (idx < 1024 ? ubr[n] : ubh[n]);
    }
}

// ---------------- input projection GEMM (f32x2) -----------------------------
__global__ __launch_bounds__(256) void input_gemm(const float* __restrict__ x) {
    __shared__ float As[16 * 132];
    __shared__ float Bs[16 * 64];
    int tid = threadIdx.x;
    int tx = tid & 15, ty = tid >> 4;
    int m0 = blockIdx.y * 128;
    int n0 = blockIdx.x * 64;

    u64 acc[8][2];
#pragma unroll
    for (int i = 0; i < 8; i++) { acc[i][0] = 0ull; acc[i][1] = 0ull; }

    for (int kt = 0; kt < 32; kt++) {
        int k0 = kt * 16;
#pragma unroll
        for (int i = 0; i < 2; i++) {
            int f = i * 256 + tid;
            int m = f >> 2, kq = f & 3;
            float4 v = *(const float4*)(x + (m0 + m) * 512 + k0 + kq * 4);
            As[(kq * 4 + 0) * 132 + m] = v.x;
            As[(kq * 4 + 1) * 132 + m] = v.y;
            As[(kq * 4 + 2) * 132 + m] = v.z;
            As[(kq * 4 + 3) * 132 + m] = v.w;
        }
        {
            int k = tid >> 4, nq = tid & 15;
            *(float4*)&Bs[k * 64 + nq * 4] =
                *(const float4*)(g_WT + (k0 + k) * 1536 + n0 + nq * 4);
        }
        __syncthreads();
#pragma unroll
        for (int kk = 0; kk < 16; kk++) {
            float4 a0 = *(const float4*)&As[kk * 132 + ty * 8];
            float4 a1 = *(const float4*)&As[kk * 132 + ty * 8 + 4];
            ulonglong2 bb = *(const ulonglong2*)&Bs[kk * 64 + tx * 4];
            u64 d0 = dupf(a0.x), d1 = dupf(a0.y), d2 = dupf(a0.z), d3 = dupf(a0.w);
            u64 d4 = dupf(a1.x), d5 = dupf(a1.y), d6 = dupf(a1.z), d7 = dupf(a1.w);
            fma2(acc[0][0], d0, bb.x); fma2(acc[0][1], d0, bb.y);
            fma2(acc[1][0], d1, bb.x); fma2(acc[1][1], d1, bb.y);
            fma2(acc[2][0], d2, bb.x); fma2(acc[2][1], d2, bb.y);
            fma2(acc[3][0], d3, bb.x); fma2(acc[3][1], d3, bb.y);
            fma2(acc[4][0], d4, bb.x); fma2(acc[4][1], d4, bb.y);
            fma2(acc[5][0], d5, bb.x); fma2(acc[5][1], d5, bb.y);
            fma2(acc[6][0], d6, bb.x); fma2(acc[6][1], d6, bb.y);
            fma2(acc[7][0], d7, bb.x); fma2(acc[7][1], d7, bb.y);
        }
        __syncthreads();
    }
#pragma unroll
    for (int i = 0; i < 8; i++) {
        int m = m0 + ty * 8 + i;
        int n = n0 + tx * 4;
        float4 o;
        float v0, v1, v2, v3;
        unpk(acc[i][0], v0, v1);
        unpk(acc[i][1], v2, v3);
        o.x = v0 + g_wbias[n + 0];
        o.y = v1 + g_wbias[n + 1];
        o.z = v2 + g_wbias[n + 2];
        o.w = v3 + g_wbias[n + 3];
        *(float4*)&g_pre[m * 1536 + n] = o;
    }
}

// ---------------- flag-array grid barrier (no atomic serialization) ---------
__device__ __forceinline__ void grid_sync(unsigned target) {
    __syncthreads();
    if (threadIdx.x == 0) {
        asm volatile("st.release.gpu.u32 [%0], %1;"
                     :: "l"(&g_flags[blockIdx.x * 32]), "r"(target) : "memory");
    }
    if (threadIdx.x < NBLK) {
        unsigned v;
        do {
            asm volatile("ld.acquire.gpu.u32 %0, [%1];"
                         : "=r"(v) : "l"(&g_flags[threadIdx.x * 32]) : "memory");
        } while (v < target);
    }
    __syncthreads();
}

// ---------------- persistent GRU scan ---------------------------------------
__global__ __launch_bounds__(256, 1) void gru_scan(const float* __restrict__ h0,
                                                   float* out) {
    extern __shared__ float smem[];
    float* hT   = smem;                         // [512][36]   73.7KB (phase1) / rT [512][20] (phase2)
    float* us   = smem + 512 * 36;              // [512][16]   32KB  zr weights (resident)
    float* u2   = us + 512 * 16;                // [512][16]   32KB  h  weights (resident)
    u64*   red  = (u64*)(u2 + 512 * 16);        // 2048 u64    16KB  reduction buf

    const int tid  = threadIdx.x;
    const int cta  = blockIdx.x;
    const int w    = tid >> 5;
    const int lane = tid & 31;

    const int bt  = cta >> 6;    // phase1: b-half 0..1
    const int nt  = cta & 63;    // phase1: n-tile 0..63
    const int bt2 = cta >> 5;    // phase2: b-tile 0..3
    const int nt2 = cta & 31;    // phase2: n-tile 0..31

    // --- resident weight tiles (step-invariant), warp-private slices ---
    {
        const float* up1 = g_Uzrp + nt * 8192;
        const float* up2 = g_Uhp + nt2 * 8192;
#pragma unroll
        for (int it = 0; it < 8; it++) {
            int off = w * 1024 + (it * 32 + lane) * 4;
            *(float4*)&us[off] = *(const float4*)(up1 + off);
            *(float4*)&u2[off] = *(const float4*)(up2 + off);
        }
    }
    // --- step-invariant epilogue constants in registers ---
    const int o1 = tid;
    const int b1l = o1 >> 3;                 // phase1 local b (0..31)
    const int b1  = bt * 32 + b1l;
    const int n1  = nt * 16 + (o1 & 7) * 2;  // phase1 n (0..1022)
    const float2 ub1 = *(const float2*)&g_ubias[n1];
    const int o2  = tid & 127;
    const int b2  = bt2 * 16 + (o2 >> 3);
    const int n2  = nt2 * 16 + (o2 & 7) * 2;
    const float2 ub2 = *(const float2*)&g_ubias[1024 + n2];

    unsigned bar = 0;

    for (int s = 0; s < S_LEN; s++) {
        const float* hprev = (s == 0) ? h0 : (out + (s - 1) * (B_DIM * 512));

        // --- prefetch epilogue operands (DRAM latency hidden under phase1) ---
        float2 pre1 = *(const float2*)&g_pre[(s * 64 + b1) * 1536 + n1];
        float2 pre2, hp2;
        if (tid < 128) {
            pre2 = *(const float2*)&g_pre[(s * 64 + b2) * 1536 + 1024 + n2];
            hp2  = *(const float2*)&hprev[b2 * 512 + n2];
        }

        // ================= Phase 1: zr = sigmoid(pre + h@Uzr^T + ub) ========
        {
            const int half = lane >> 4, l16 = lane & 15;
#pragma unroll
            for (int it = 0; it < 16; it++) {            // hT: 32b x 64k slice
                int b = it * 2 + half;
                int j = w * 64 + l16 * 4;
                float4 v = *(const float4*)(hprev + (bt * 32 + b) * 512 + j);
                hT[(j + 0) * 36 + b] = v.x;
                hT[(j + 1) * 36 + b] = v.y;
                hT[(j + 2) * 36 + b] = v.z;
                hT[(j + 3) * 36 + b] = v.w;
            }
            const int bg = lane >> 2;        // b0 = bg*4
            const int ng = lane & 3;         // n0 = ng*4
            u64 acc[4][2];
#pragma unroll
            for (int i = 0; i < 4; i++) { acc[i][0] = 0ull; acc[i][1] = 0ull; }
#pragma unroll 16
            for (int kk = 0; kk < 64; kk++) {
                int k = w * 64 + kk;
                ulonglong2 uu = *(const ulonglong2*)(us + k * 16 + ng * 4);
                float4 hv = *(const float4*)(hT + k * 36 + bg * 4);
                u64 h0p = dupf(hv.x), h1p = dupf(hv.y), h2p = dupf(hv.z), h3p = dupf(hv.w);
                fma2(acc[0][0], h0p, uu.x); fma2(acc[0][1], h0p, uu.y);
                fma2(acc[1][0], h1p, uu.x); fma2(acc[1][1], h1p, uu.y);
                fma2(acc[2][0], h2p, uu.x); fma2(acc[2][1], h2p, uu.y);
                fma2(acc[3][0], h3p, uu.x); fma2(acc[3][1], h3p, uu.y);
            }
            int rb = w * 256 + bg * 32 + ng * 2;
#pragma unroll
            for (int i = 0; i < 4; i++) {
                red[rb + i * 8 + 0] = acc[i][0];
                red[rb + i * 8 + 1] = acc[i][1];
            }
            __syncthreads();
            {
                u64 ssum = red[o1];
#pragma unroll
                for (int p = 1; p < 8; p++) ssum = add2(ssum, red[p * 256 + o1]);
                float s0, s1; unpk(ssum, s0, s1);
                float a0 = pre1.x + s0 + ub1.x;
                float a1 = pre1.y + s1 + ub1.y;
                float v0 = 1.f / (1.f + __expf(-a0));
                float v1 = 1.f / (1.f + __expf(-a1));
                if (nt < 32) {
                    g_z[b1 * 512 + n1]     = v0;
                    g_z[b1 * 512 + n1 + 1] = v1;
                } else {
                    int j = n1 - 512;
                    g_rh[b1 * 512 + j]     = v0 * hT[j * 36 + b1l];
                    g_rh[b1 * 512 + j + 1] = v1 * hT[(j + 1) * 36 + b1l];
                }
            }
        }
        grid_sync(++bar);

        // ================= Phase 2: h~ = tanh(pre + rh@Uh^T + ub) ===========
        {
            float* rT = hT;                  // reuse, pitch 20
            const int half = lane >> 4, l16 = lane & 15;
#pragma unroll
            for (int it = 0; it < 8; it++) {             // rT: 16b x 64k slice
                int b = it * 2 + half;
                int j = w * 64 + l16 * 4;
                float4 v = *(const float4*)(g_rh + (bt2 * 16 + b) * 512 + j);
                rT[(j + 0) * 20 + b] = v.x;
                rT[(j + 1) * 20 + b] = v.y;
                rT[(j + 2) * 20 + b] = v.z;
                rT[(j + 3) * 20 + b] = v.w;
            }
            const int bg = lane >> 2;        // b0 = bg*2
            const int ng = lane & 3;         // n0 = ng*4
            u64 acc[2][2];
            acc[0][0] = acc[0][1] = acc[1][0] = acc[1][1] = 0ull;
#pragma unroll 16
            for (int kk = 0; kk < 64; kk++) {
                int k = w * 64 + kk;
                ulonglong2 uu = *(const ulonglong2*)(u2 + k * 16 + ng * 4);
                float2 rv = *(const float2*)(rT + k * 20 + bg * 2);
                u64 r0p = dupf(rv.x), r1p = dupf(rv.y);
                fma2(acc[0][0], r0p, uu.x); fma2(acc[0][1], r0p, uu.y);
                fma2(acc[1][0], r1p, uu.x); fma2(acc[1][1], r1p, uu.y);
            }
            int rb = w * 128 + bg * 16 + ng * 2;
            red[rb + 0] = acc[0][0];
            red[rb + 1] = acc[0][1];
            red[rb + 8] = acc[1][0];
            red[rb + 9] = acc[1][1];
            __syncthreads();
            if (tid < 128) {
                u64 ssum = red[o2];
#pragma unroll
                for (int p = 1; p < 8; p++) ssum = add2(ssum, red[p * 128 + o2]);
                float s0, s1; unpk(ssum, s0, s1);
                float z0 = g_z[b2 * 512 + n2];
                float z1 = g_z[b2 * 512 + n2 + 1];
                float a0 = pre2.x + s0 + ub2.x;
                float a1 = pre2.y + s1 + ub2.y;
                float e0 = __expf(2.f * a0), e1 = __expf(2.f * a1);
                float t0 = 1.f - 2.f / (e0 + 1.f);
                float t1 = 1.f - 2.f / (e1 + 1.f);
                float hn0 = hp2.x + z0 * (t0 - hp2.x);
                float hn1 = hp2.y + z1 * (t1 - hp2.y);
                float2 o = make_float2(hn0, hn1);
                *(float2*)&out[s * (B_DIM * 512) + b2 * 512 + n2] = o;
                if (s == S_LEN - 1)
                    *(float2*)&out[S_LEN * (B_DIM * 512) + b2 * 512 + n2] = o;
            }
        }
        grid_sync(++bar);
    }
}

// ---------------- launch ----------------------------------------------------
extern "C" void kernel_launch(void* const* d_in, const int* in_sizes, int n_in,
                              void* d_out, int out_size) {
    (void)in_sizes; (void)n_in; (void)out_size;
    const float* x    = (const float*)d_in[0];
    const float* h0   = (const float*)d_in[1];
    const float* Wz_w = (const float*)d_in[2];
    const float* Wz_b = (const float*)d_in[3];
    const float* Uz_w = (const float*)d_in[4];
    const float* Uz_b = (const float*)d_in[5];
    const float* Wr_w = (const float*)d_in[6];
    const float* Wr_b = (const float*)d_in[7];
    const float* Ur_w = (const float*)d_in[8];
    const float* Ur_b = (const float*)d_in[9];
    const float* Wh_w = (const float*)d_in[10];
    const float* Wh_b = (const float*)d_in[11];
    const float* Uh_w = (const float*)d_in[12];
    const float* Uh_b = (const float*)d_in[13];
    float* out = (float*)d_out;

    static int smem_set = 0;
    if (!smem_set) {
        cudaFuncSetAttribute(gru_scan, cudaFuncAttributeMaxDynamicSharedMemorySize,
                             155648);
        smem_set = 1;
    }

    pack_kernel<<<256, 256>>>(Wz_w, Wz_b, Uz_w, Uz_b,
                              Wr_w, Wr_b, Ur_w, Ur_b,
                              Wh_w, Wh_b, Uh_w, Uh_b);
    input_gemm<<<dim3(24, 512), 256>>>(x);
    gru_scan<<<NBLK, 256, 155648>>>(h0, out);
}

// round 4
// speedup vs baseline: 1.5793x; 1.2229x over previous
#include <cuda_runtime.h>
#include <math.h>

#define S_LEN 1024
#define B_DIM 64
#define NBLK  128

typedef unsigned long long u64;

// ---------------- f32x2 helpers (sm_100+) -----------------------------------
__device__ __forceinline__ u64 dupf(float x) {
    u64 r; unsigned xi = __float_as_uint(x);
    asm("mov.b64 %0, {%1, %1};" : "=l"(r) : "r"(xi));
    return r;
}
__device__ __forceinline__ void fma2(u64& d, u64 a, u64 b) {
    asm("fma.rn.f32x2 %0, %1, %2, %0;" : "+l"(d) : "l"(a), "l"(b));
}
__device__ __forceinline__ u64 add2(u64 a, u64 b) {
    u64 d; asm("add.rn.f32x2 %0, %1, %2;" : "=l"(d) : "l"(a), "l"(b));
    return d;
}
__device__ __forceinline__ void unpk(u64 p, float& lo, float& hi) {
    unsigned a, b;
    asm("mov.b64 {%0, %1}, %2;" : "=r"(a), "=r"(b) : "l"(p));
    lo = __uint_as_float(a); hi = __uint_as_float(b);
}

// swizzled chunk column for 32-row tiles (phase 1)
__device__ __forceinline__ int swz1(int b, int c) {
    return c ^ ((b >> 2) & 7) ^ ((c >> 4) & 7) ^ ((b & 3) << 1);
}
// swizzled chunk column for 16-row tiles (phase 2)
__device__ __forceinline__ int swz2(int b, int c) {
    return c ^ ((b >> 1) & 7) ^ ((c >> 4) & 7) ^ ((b & 1) << 2);
}

// ---------------- device scratch --------------------------------------------
__device__ float g_pre[S_LEN * B_DIM * 1536];   // xz|xr|xh preactivations
__device__ float g_WT[512 * 1536];              // [k][n] input weights (k-major)
__device__ float g_Uzrp[64 * 512 * 16];         // packed [nt][k][16n] zr weights
__device__ float g_Uhp[32 * 512 * 16];          // packed [nt][k][16n] h weights
__device__ float g_wbias[1536];
__device__ float g_ubias[1536];
__device__ float g_z[B_DIM * 512];
__device__ float g_rh[B_DIM * 512];
__device__ unsigned g_flags[NBLK * 32];         // per-CTA barrier flags, 128B stride

// ---------------- pack + flag reset -----------------------------------------
__global__ void pack_kernel(const float* Wz, const float* bz, const float* Uz, const float* ubz,
                            const float* Wr, const float* br, const float* Ur, const float* ubr,
                            const float* Wh, const float* bh, const float* Uh, const float* ubh) {
    int stride = gridDim.x * blockDim.x;
    int t = blockIdx.x * blockDim.x + threadIdx.x;
    for (int idx = t; idx < NBLK * 32; idx += stride) g_flags[idx] = 0u;
    for (int idx = t; idx < 512 * 1536; idx += stride) {
        int k = idx / 1536, n = idx % 1536;
        const float* W = (n < 512) ? Wz : (n < 1024 ? Wr : Wh);
        g_WT[idx] = W[(n & 511) * 512 + k];
    }
    for (int idx = t; idx < 64 * 512 * 16; idx += stride) {
        int nt = idx >> 13, k = (idx >> 4) & 511, nn = idx & 15;
        int n = nt * 16 + nn;
        g_Uzrp[idx] = (n < 512) ? Uz[n * 512 + k] : Ur[(n - 512) * 512 + k];
    }
    for (int idx = t; idx < 32 * 512 * 16; idx += stride) {
        int nt = idx >> 13, k = (idx >> 4) & 511, nn = idx & 15;
        g_Uhp[idx] = Uh[(nt * 16 + nn) * 512 + k];
    }
    for (int idx = t; idx < 1536; idx += stride) {
        int n = idx & 511;
        g_wbias[idx] = (idx < 512) ? bz[n] : (idx < 1024 ? br[n] : bh[n]);
        g_ubias[idx] = (idx < 512) ? ubz[n] : (idx < 1024 ? ubr[n] : ubh[n]);
    }
}

// ---------------- input projection GEMM (f32x2) -----------------------------
__global__ __launch_bounds__(256) void input_gemm(const float* __restrict__ x) {
    __shared__ float As[16 * 132];
    __shared__ float Bs[16 * 64];
    int tid = threadIdx.x;
    int tx = tid & 15, ty = tid >> 4;
    int m0 = blockIdx.y * 128;
    int n0 = blockIdx.x * 64;

    u64 acc[8][2];
#pragma unroll
    for (int i = 0; i < 8; i++) { acc[i][0] = 0ull; acc[i][1] = 0ull; }

    for (int kt = 0; kt < 32; kt++) {
        int k0 = kt * 16;
#pragma unroll
        for (int i = 0; i < 2; i++) {
            int f = i * 256 + tid;
            int m = f >> 2, kq = f & 3;
            float4 v = *(const float4*)(x + (m0 + m) * 512 + k0 + kq * 4);
            As[(kq * 4 + 0) * 132 + m] = v.x;
            As[(kq * 4 + 1) * 132 + m] = v.y;
            As[(kq * 4 + 2) * 132 + m] = v.z;
            As[(kq * 4 + 3) * 132 + m] = v.w;
        }
        {
            int k = tid >> 4, nq = tid & 15;
            *(float4*)&Bs[k * 64 + nq * 4] =
                *(const float4*)(g_WT + (k0 + k) * 1536 + n0 + nq * 4);
        }
        __syncthreads();
#pragma unroll
        for (int kk = 0; kk < 16; kk++) {
            float4 a0 = *(const float4*)&As[kk * 132 + ty * 8];
            float4 a1 = *(const float4*)&As[kk * 132 + ty * 8 + 4];
            ulonglong2 bb = *(const ulonglong2*)&Bs[kk * 64 + tx * 4];
            u64 d0 = dupf(a0.x), d1 = dupf(a0.y), d2 = dupf(a0.z), d3 = dupf(a0.w);
            u64 d4 = dupf(a1.x), d5 = dupf(a1.y), d6 = dupf(a1.z), d7 = dupf(a1.w);
            fma2(acc[0][0], d0, bb.x); fma2(acc[0][1], d0, bb.y);
            fma2(acc[1][0], d1, bb.x); fma2(acc[1][1], d1, bb.y);
            fma2(acc[2][0], d2, bb.x); fma2(acc[2][1], d2, bb.y);
            fma2(acc[3][0], d3, bb.x); fma2(acc[3][1], d3, bb.y);
            fma2(acc[4][0], d4, bb.x); fma2(acc[4][1], d4, bb.y);
            fma2(acc[5][0], d5, bb.x); fma2(acc[5][1], d5, bb.y);
            fma2(acc[6][0], d6, bb.x); fma2(acc[6][1], d6, bb.y);
            fma2(acc[7][0], d7, bb.x); fma2(acc[7][1], d7, bb.y);
        }
        __syncthreads();
    }
#pragma unroll
    for (int i = 0; i < 8; i++) {
        int m = m0 + ty * 8 + i;
        int n = n0 + tx * 4;
        float4 o;
        float v0, v1, v2, v3;
        unpk(acc[i][0], v0, v1);
        unpk(acc[i][1], v2, v3);
        o.x = v0 + g_wbias[n + 0];
        o.y = v1 + g_wbias[n + 1];
        o.z = v2 + g_wbias[n + 2];
        o.w = v3 + g_wbias[n + 3];
        *(float4*)&g_pre[m * 1536 + n] = o;
    }
}

// ---------------- flag-array grid barrier ------------------------------------
__device__ __forceinline__ void grid_sync(unsigned target) {
    __syncthreads();
    if (threadIdx.x == 0) {
        asm volatile("st.release.gpu.u32 [%0], %1;"
                     :: "l"(&g_flags[blockIdx.x * 32]), "r"(target) : "memory");
    }
    if (threadIdx.x < NBLK) {
        unsigned v;
        do {
            asm volatile("ld.acquire.gpu.u32 %0, [%1];"
                         : "=r"(v) : "l"(&g_flags[threadIdx.x * 32]) : "memory");
        } while (v < target);
    }
    __syncthreads();
}

// ---------------- persistent GRU scan ---------------------------------------
__global__ __launch_bounds__(256, 1) void gru_scan(const float* __restrict__ h0,
                                                   float* out) {
    extern __shared__ float smem[];
    float4* hs4 = (float4*)smem;                // [32][128] chunks, swizzled; 64KB
    float*  us  = smem + 16384;                 // [512][16]  32KB  zr weights
    float*  u2  = us + 8192;                    // [512][16]  32KB  h  weights
    u64*    red = (u64*)(u2 + 8192);            // 2048 u64   16KB

    const int tid  = threadIdx.x;
    const int cta  = blockIdx.x;
    const int w    = tid >> 5;
    const int lane = tid & 31;

    const int bt  = cta >> 6;    // phase1: b-half 0..1
    const int nt  = cta & 63;    // phase1: n-tile 0..63
    const int bt2 = cta >> 5;    // phase2: b-tile 0..3
    const int nt2 = cta & 31;    // phase2: n-tile 0..31

    // --- resident weight tiles (step-invariant), warp-private slices ---
    {
        const float* up1 = g_Uzrp + nt * 8192;
        const float* up2 = g_Uhp + nt2 * 8192;
#pragma unroll
        for (int it = 0; it < 8; it++) {
            int off = w * 1024 + (it * 32 + lane) * 4;
            *(float4*)&us[off] = *(const float4*)(up1 + off);
            *(float4*)&u2[off] = *(const float4*)(up2 + off);
        }
    }
    // --- step-invariant epilogue constants ---
    const int o1 = tid;
    const int b1l = o1 >> 3;                 // phase1 local b (0..31)
    const int b1  = bt * 32 + b1l;
    const int n1  = nt * 16 + (o1 & 7) * 2;  // phase1 n (0..1022)
    const float2 ub1 = *(const float2*)&g_ubias[n1];
    const int o2  = tid & 127;
    const int b2  = bt2 * 16 + (o2 >> 3);
    const int n2  = nt2 * 16 + (o2 & 7) * 2;
    const float2 ub2 = *(const float2*)&g_ubias[1024 + n2];

    const int bg = lane >> 2;                // 0..7
    const int ng = lane & 3;                 // 0..3
    const int cxor = w & 7;

    unsigned bar = 0;

    for (int s = 0; s < S_LEN; s++) {
        const float* hprev = (s == 0) ? h0 : (out + (s - 1) * (B_DIM * 512));

        // --- prefetch epilogue operands ---
        float2 pre1 = *(const float2*)&g_pre[(s * 64 + b1) * 1536 + n1];
        float2 pre2, hp2;
        if (tid < 128) {
            pre2 = *(const float2*)&g_pre[(s * 64 + b2) * 1536 + 1024 + n2];
            hp2  = *(const float2*)&hprev[b2 * 512 + n2];
        }

        // ================= Phase 1: zr = sigmoid(pre + h@Uzr^T + ub) ========
        {
            // cooperative coalesced load of h tile [32b][512k] into swizzled hs4
            {
                int lb = w * 4 + (lane >> 3);        // 0..31
                int cl = lane & 7;
                const float4* hp4 = (const float4*)(hprev + (bt * 32 + lb) * 512);
#pragma unroll
                for (int q = 0; q < 16; q++) {
                    int c = q * 8 + cl;
                    hs4[lb * 128 + swz1(lb, c)] = hp4[c];
                }
            }
            __syncthreads();

            u64 acc[4][2];
#pragma unroll
            for (int i = 0; i < 4; i++) { acc[i][0] = 0ull; acc[i][1] = 0ull; }
            const float4* hrow0 = hs4 + (bg * 4 + 0) * 128;
            const float4* hrow1 = hs4 + (bg * 4 + 1) * 128;
            const float4* hrow2 = hs4 + (bg * 4 + 2) * 128;
            const float4* hrow3 = hs4 + (bg * 4 + 3) * 128;
            const int s0 = bg ^ 0, s1 = bg ^ 2, s2 = bg ^ 4, s3 = bg ^ 6;
            const float* upc = us + ng * 4;
#pragma unroll
            for (int cc = 0; cc < 16; cc++) {
                int cb = w * 16 + cc;
                int cx = cb ^ cxor;
                float4 hv0 = hrow0[cx ^ s0];
                float4 hv1 = hrow1[cx ^ s1];
                float4 hv2 = hrow2[cx ^ s2];
                float4 hv3 = hrow3[cx ^ s3];
                ulonglong2 uu0 = *(const ulonglong2*)(upc + (cb * 4 + 0) * 16);
                ulonglong2 uu1 = *(const ulonglong2*)(upc + (cb * 4 + 1) * 16);
                ulonglong2 uu2 = *(const ulonglong2*)(upc + (cb * 4 + 2) * 16);
                ulonglong2 uu3 = *(const ulonglong2*)(upc + (cb * 4 + 3) * 16);
                u64 d;
                d = dupf(hv0.x); fma2(acc[0][0], d, uu0.x); fma2(acc[0][1], d, uu0.y);
                d = dupf(hv1.x); fma2(acc[1][0], d, uu0.x); fma2(acc[1][1], d, uu0.y);
                d = dupf(hv2.x); fma2(acc[2][0], d, uu0.x); fma2(acc[2][1], d, uu0.y);
                d = dupf(hv3.x); fma2(acc[3][0], d, uu0.x); fma2(acc[3][1], d, uu0.y);
                d = dupf(hv0.y); fma2(acc[0][0], d, uu1.x); fma2(acc[0][1], d, uu1.y);
                d = dupf(hv1.y); fma2(acc[1][0], d, uu1.x); fma2(acc[1][1], d, uu1.y);
                d = dupf(hv2.y); fma2(acc[2][0], d, uu1.x); fma2(acc[2][1], d, uu1.y);
                d = dupf(hv3.y); fma2(acc[3][0], d, uu1.x); fma2(acc[3][1], d, uu1.y);
                d = dupf(hv0.z); fma2(acc[0][0], d, uu2.x); fma2(acc[0][1], d, uu2.y);
                d = dupf(hv1.z); fma2(acc[1][0], d, uu2.x); fma2(acc[1][1], d, uu2.y);
                d = dupf(hv2.z); fma2(acc[2][0], d, uu2.x); fma2(acc[2][1], d, uu2.y);
                d = dupf(hv3.z); fma2(acc[3][0], d, uu2.x); fma2(acc[3][1], d, uu2.y);
                d = dupf(hv0.w); fma2(acc[0][0], d, uu3.x); fma2(acc[0][1], d, uu3.y);
                d = dupf(hv1.w); fma2(acc[1][0], d, uu3.x); fma2(acc[1][1], d, uu3.y);
                d = dupf(hv2.w); fma2(acc[2][0], d, uu3.x); fma2(acc[2][1], d, uu3.y);
                d = dupf(hv3.w); fma2(acc[3][0], d, uu3.x); fma2(acc[3][1], d, uu3.y);
            }
            int rb = w * 256 + bg * 32 + ng * 2;
#pragma unroll
            for (int i = 0; i < 4; i++) {
                red[rb + i * 8 + 0] = acc[i][0];
                red[rb + i * 8 + 1] = acc[i][1];
            }
            __syncthreads();
            {
                u64 ssum = red[o1];
#pragma unroll
                for (int p = 1; p < 8; p++) ssum = add2(ssum, red[p * 256 + o1]);
                float v0s, v1s; unpk(ssum, v0s, v1s);
                float a0 = pre1.x + v0s + ub1.x;
                float a1 = pre1.y + v1s + ub1.y;
                float v0 = 1.f / (1.f + __expf(-a0));
                float v1 = 1.f / (1.f + __expf(-a1));
                if (nt < 32) {
                    g_z[b1 * 512 + n1]     = v0;
                    g_z[b1 * 512 + n1 + 1] = v1;
                } else {
                    int j = n1 - 512;
                    int c = j >> 2;
                    const float* ch = (const float*)&hs4[b1l * 128 + swz1(b1l, c)];
                    g_rh[b1 * 512 + j]     = v0 * ch[j & 3];
                    g_rh[b1 * 512 + j + 1] = v1 * ch[(j & 3) + 1];
                }
            }
        }
        grid_sync(++bar);

        // ================= Phase 2: h~ = tanh(pre + rh@Uh^T + ub) ===========
        {
            float4* rs4 = hs4;               // reuse, [16][128] chunks swizzled
            {
                int lb = w * 2 + (lane >> 4);        // 0..15
                int cl = lane & 15;
                const float4* rp4 = (const float4*)(g_rh + (bt2 * 16 + lb) * 512);
#pragma unroll
                for (int q = 0; q < 8; q++) {
                    int c = q * 16 + cl;
                    rs4[lb * 128 + swz2(lb, c)] = rp4[c];
                }
            }
            __syncthreads();

            u64 acc[2][2];
            acc[0][0] = acc[0][1] = acc[1][0] = acc[1][1] = 0ull;
            const float4* rrow0 = rs4 + (bg * 2 + 0) * 128;
            const float4* rrow1 = rs4 + (bg * 2 + 1) * 128;
            const int t0 = bg ^ 0, t1 = bg ^ 4;
            const float* upc = u2 + ng * 4;
#pragma unroll
            for (int cc = 0; cc < 16; cc++) {
                int cb = w * 16 + cc;
                int cx = cb ^ cxor;
                float4 rv0 = rrow0[cx ^ t0];
                float4 rv1 = rrow1[cx ^ t1];
                ulonglong2 uu0 = *(const ulonglong2*)(upc + (cb * 4 + 0) * 16);
                ulonglong2 uu1 = *(const ulonglong2*)(upc + (cb * 4 + 1) * 16);
                ulonglong2 uu2 = *(const ulonglong2*)(upc + (cb * 4 + 2) * 16);
                ulonglong2 uu3 = *(const ulonglong2*)(upc + (cb * 4 + 3) * 16);
                u64 d;
                d = dupf(rv0.x); fma2(acc[0][0], d, uu0.x); fma2(acc[0][1], d, uu0.y);
                d = dupf(rv1.x); fma2(acc[1][0], d, uu0.x); fma2(acc[1][1], d, uu0.y);
                d = dupf(rv0.y); fma2(acc[0][0], d, uu1.x); fma2(acc[0][1], d, uu1.y);
                d = dupf(rv1.y); fma2(acc[1][0], d, uu1.x); fma2(acc[1][1], d, uu1.y);
                d = dupf(rv0.z); fma2(acc[0][0], d, uu2.x); fma2(acc[0][1], d, uu2.y);
                d = dupf(rv1.z); fma2(acc[1][0], d, uu2.x); fma2(acc[1][1], d, uu2.y);
                d = dupf(rv0.w); fma2(acc[0][0], d, uu3.x); fma2(acc[0][1], d, uu3.y);
                d = dupf(rv1.w); fma2(acc[1][0], d, uu3.x); fma2(acc[1][1], d, uu3.y);
            }
            int rb = w * 128 + bg * 16 + ng * 2;
            red[rb + 0] = acc[0][0];
            red[rb + 1] = acc[0][1];
            red[rb + 8] = acc[1][0];
            red[rb + 9] = acc[1][1];
            __syncthreads();
            if (tid < 128) {
                u64 ssum = red[o2];
#pragma unroll
                for (int p = 1; p < 8; p++) ssum = add2(ssum, red[p * 128 + o2]);
                float v0s, v1s; unpk(ssum, v0s, v1s);
                float z0 = g_z[b2 * 512 + n2];
                float z1 = g_z[b2 * 512 + n2 + 1];
                float a0 = pre2.x + v0s + ub2.x;
                float a1 = pre2.y + v1s + ub2.y;
                float e0 = __expf(2.f * a0), e1 = __expf(2.f * a1);
                float th0 = 1.f - 2.f / (e0 + 1.f);
                float th1 = 1.f - 2.f / (e1 + 1.f);
                float hn0 = hp2.x + z0 * (th0 - hp2.x);
                float hn1 = hp2.y + z1 * (th1 - hp2.y);
                float2 o = make_float2(hn0, hn1);
                *(float2*)&out[s * (B_DIM * 512) + b2 * 512 + n2] = o;
                if (s == S_LEN - 1)
                    *(float2*)&out[S_LEN * (B_DIM * 512) + b2 * 512 + n2] = o;
            }
        }
        grid_sync(++bar);
    }
}

// ---------------- launch ----------------------------------------------------
extern "C" void kernel_launch(void* const* d_in, const int* in_sizes, int n_in,
                              void* d_out, int out_size) {
    (void)in_sizes; (void)n_in; (void)out_size;
    const float* x    = (const float*)d_in[0];
    const float* h0   = (const float*)d_in[1];
    const float* Wz_w = (const float*)d_in[2];
    const float* Wz_b = (const float*)d_in[3];
    const float* Uz_w = (const float*)d_in[4];
    const float* Uz_b = (const float*)d_in[5];
    const float* Wr_w = (const float*)d_in[6];
    const float* Wr_b = (const float*)d_in[7];
    const float* Ur_w = (const float*)d_in[8];
    const float* Ur_b = (const float*)d_in[9];
    const float* Wh_w = (const float*)d_in[10];
    const float* Wh_b = (const float*)d_in[11];
    const float* Uh_w = (const float*)d_in[12];
    const float* Uh_b = (const float*)d_in[13];
    float* out = (float*)d_out;

    static int smem_set = 0;
    if (!smem_set) {
        cudaFuncSetAttribute(gru_scan, cudaFuncAttributeMaxDynamicSharedMemorySize,
                             147456);
        smem_set = 1;
    }

    pack_kernel<<<256, 256>>>(Wz_w, Wz_b, Uz_w, Uz_b,
                              Wr_w, Wr_b, Ur_w, Ur_b,
                              Wh_w, Wh_b, Uh_w, Uh_b);
    input_gemm<<<dim3(24, 512), 256>>>(x);
    gru_scan<<<NBLK, 256, 147456>>>(h0, out);
}

// round 5
// speedup vs baseline: 1.6394x; 1.0381x over previous
#include <cuda_runtime.h>
#include <math.h>

#define S_LEN 1024
#define B_DIM 64
#define NBLK  128
#define GRP_CTAS 32

typedef unsigned long long u64;

// ---------------- f32x2 helpers (sm_100+) -----------------------------------
__device__ __forceinline__ u64 dupf(float x) {
    u64 r; unsigned xi = __float_as_uint(x);
    asm("mov.b64 %0, {%1, %1};" : "=l"(r) : "r"(xi));
    return r;
}
__device__ __forceinline__ void fma2(u64& d, u64 a, u64 b) {
    asm("fma.rn.f32x2 %0, %1, %2, %0;" : "+l"(d) : "l"(a), "l"(b));
}
__device__ __forceinline__ u64 add2(u64 a, u64 b) {
    u64 d; asm("add.rn.f32x2 %0, %1, %2;" : "=l"(d) : "l"(a), "l"(b));
    return d;
}
__device__ __forceinline__ void unpk(u64 p, float& lo, float& hi) {
    unsigned a, b;
    asm("mov.b64 {%0, %1}, %2;" : "=r"(a), "=r"(b) : "l"(p));
    lo = __uint_as_float(a); hi = __uint_as_float(b);
}

// swizzled chunk column for 16-row tiles
__device__ __forceinline__ int swz2(int b, int c) {
    return c ^ ((b >> 1) & 7) ^ ((c >> 4) & 7) ^ ((b & 1) << 2);
}

// ---------------- device scratch --------------------------------------------
__device__ float g_pre[S_LEN * B_DIM * 1536];   // xz|xr|xh preactivations
__device__ float g_WT[512 * 1536];              // [k][n] input weights (k-major)
__device__ float g_Uzrp[32 * 512 * 32];         // packed [cl][k][32n] zr weights
__device__ float g_Uhp[32 * 512 * 16];          // packed [cl][k][16n] h weights
__device__ float g_wbias[1536];
__device__ float g_ubias[1536];
__device__ float g_z[B_DIM * 512];
__device__ float g_rh[B_DIM * 512];
__device__ unsigned g_flags[NBLK * 32];         // per-CTA barrier flags, 128B stride

// ---------------- pack + flag reset -----------------------------------------
__global__ void pack_kernel(const float* Wz, const float* bz, const float* Uz, const float* ubz,
                            const float* Wr, const float* br, const float* Ur, const float* ubr,
                            const float* Wh, const float* bh, const float* Uh, const float* ubh) {
    int stride = gridDim.x * blockDim.x;
    int t = blockIdx.x * blockDim.x + threadIdx.x;
    for (int idx = t; idx < NBLK * 32; idx += stride) g_flags[idx] = 0u;
    for (int idx = t; idx < 512 * 1536; idx += stride) {
        int k = idx / 1536, n = idx % 1536;
        const float* W = (n < 512) ? Wz : (n < 1024 ? Wr : Wh);
        g_WT[idx] = W[(n & 511) * 512 + k];
    }
    for (int idx = t; idx < 32 * 512 * 32; idx += stride) {
        int cl = idx >> 14, k = (idx >> 5) & 511, nn = idx & 31;
        int n = cl * 32 + nn;
        g_Uzrp[idx] = (n < 512) ? Uz[n * 512 + k] : Ur[(n - 512) * 512 + k];
    }
    for (int idx = t; idx < 32 * 512 * 16; idx += stride) {
        int cl = idx >> 13, k = (idx >> 4) & 511, nn = idx & 15;
        g_Uhp[idx] = Uh[(cl * 16 + nn) * 512 + k];
    }
    for (int idx = t; idx < 1536; idx += stride) {
        int n = idx & 511;
        g_wbias[idx] = (idx < 512) ? bz[n] : (idx < 1024 ? br[n] : bh[n]);
        g_ubias[idx] = (idx < 512) ? ubz[n] : (idx < 1024 ? ubr[n] : ubh[n]);
    }
}

// ---------------- input projection GEMM (f32x2) -----------------------------
__global__ __launch_bounds__(256) void input_gemm(const float* __restrict__ x) {
    __shared__ float As[16 * 132];
    __shared__ float Bs[16 * 64];
    int tid = threadIdx.x;
    int tx = tid & 15, ty = tid >> 4;
    int m0 = blockIdx.y * 128;
    int n0 = blockIdx.x * 64;

    u64 acc[8][2];
#pragma unroll
    for (int i = 0; i < 8; i++) { acc[i][0] = 0ull; acc[i][1] = 0ull; }

    for (int kt = 0; kt < 32; kt++) {
        int k0 = kt * 16;
#pragma unroll
        for (int i = 0; i < 2; i++) {
            int f = i * 256 + tid;
            int m = f >> 2, kq = f & 3;
            float4 v = *(const float4*)(x + (m0 + m) * 512 + k0 + kq * 4);
            As[(kq * 4 + 0) * 132 + m] = v.x;
            As[(kq * 4 + 1) * 132 + m] = v.y;
            As[(kq * 4 + 2) * 132 + m] = v.z;
            As[(kq * 4 + 3) * 132 + m] = v.w;
        }
        {
            int k = tid >> 4, nq = tid & 15;
            *(float4*)&Bs[k * 64 + nq * 4] =
                *(const float4*)(g_WT + (k0 + k) * 1536 + n0 + nq * 4);
        }
        __syncthreads();
#pragma unroll
        for (int kk = 0; kk < 16; kk++) {
            float4 a0 = *(const float4*)&As[kk * 132 + ty * 8];
            float4 a1 = *(const float4*)&As[kk * 132 + ty * 8 + 4];
            ulonglong2 bb = *(const ulonglong2*)&Bs[kk * 64 + tx * 4];
            u64 d0 = dupf(a0.x), d1 = dupf(a0.y), d2 = dupf(a0.z), d3 = dupf(a0.w);
            u64 d4 = dupf(a1.x), d5 = dupf(a1.y), d6 = dupf(a1.z), d7 = dupf(a1.w);
            fma2(acc[0][0], d0, bb.x); fma2(acc[0][1], d0, bb.y);
            fma2(acc[1][0], d1, bb.x); fma2(acc[1][1], d1, bb.y);
            fma2(acc[2][0], d2, bb.x); fma2(acc[2][1], d2, bb.y);
            fma2(acc[3][0], d3, bb.x); fma2(acc[3][1], d3, bb.y);
            fma2(acc[4][0], d4, bb.x); fma2(acc[4][1], d4, bb.y);
            fma2(acc[5][0], d5, bb.x); fma2(acc[5][1], d5, bb.y);
            fma2(acc[6][0], d6, bb.x); fma2(acc[6][1], d6, bb.y);
            fma2(acc[7][0], d7, bb.x); fma2(acc[7][1], d7, bb.y);
        }
        __syncthreads();
    }
#pragma unroll
    for (int i = 0; i < 8; i++) {
        int m = m0 + ty * 8 + i;
        int n = n0 + tx * 4;
        float4 o;
        float v0, v1, v2, v3;
        unpk(acc[i][0], v0, v1);
        unpk(acc[i][1], v2, v3);
        o.x = v0 + g_wbias[n + 0];
        o.y = v1 + g_wbias[n + 1];
        o.z = v2 + g_wbias[n + 2];
        o.w = v3 + g_wbias[n + 3];
        *(float4*)&g_pre[m * 1536 + n] = o;
    }
}

// ---------------- per-group barrier (32 CTAs) -------------------------------
__device__ __forceinline__ void group_sync(int gbase, unsigned target) {
    __syncthreads();
    if (threadIdx.x == 0) {
        asm volatile("st.release.gpu.u32 [%0], %1;"
                     :: "l"(&g_flags[blockIdx.x * 32]), "r"(target) : "memory");
    }
    if (threadIdx.x < GRP_CTAS) {
        unsigned v;
        const unsigned* fp = &g_flags[(gbase + threadIdx.x) * 32];
        do {
            asm volatile("ld.acquire.gpu.u32 %0, [%1];"
                         : "=r"(v) : "l"(fp) : "memory");
        } while (v < target);
    }
    __syncthreads();
}

// ---------------- persistent GRU scan: 4 independent groups -----------------
// group g = cta>>5 owns batch rows [g*16, g*16+16) for all 1024 steps.
// Within group (cl = cta&31):
//   P1: zr tile 16b x 32n x 512k  (n = cl*32), K split across 8 warps
//   P2: h~ tile 16b x 16n x 512k  (n = cl*16)
__global__ __launch_bounds__(256, 1) void gru_scan(const float* __restrict__ h0,
                                                   float* out) {
    extern __shared__ float smem[];
    float4* hs4 = (float4*)smem;                // [16][128] chunks swizzled, 32KB
    float4* rs4 = hs4 + 2048;                   // [16][128] chunks swizzled, 32KB
    float*  us  = smem + 16384;                 // [512][32]  64KB zr weights
    float*  u2  = smem + 32768;                 // [512][16]  32KB h  weights
    u64*    red = (u64*)(smem + 40960);         // 2048 u64   16KB

    const int tid  = threadIdx.x;
    const int cta  = blockIdx.x;
    const int w    = tid >> 5;
    const int lane = tid & 31;
    const int g    = cta >> 5;
    const int cl   = cta & 31;
    const int gbase = cta & ~(GRP_CTAS - 1);
    const int gb0  = g * 16;                    // group batch base

    // --- resident weights ---
    {
        const float* up1 = g_Uzrp + cl * 16384;
#pragma unroll
        for (int i = 0; i < 16; i++) {
            int off = (i * 256 + tid) * 4;
            *(float4*)&us[off] = *(const float4*)(up1 + off);
        }
        const float* up2 = g_Uhp + cl * 8192;
#pragma unroll
        for (int i = 0; i < 8; i++) {
            int off = (i * 256 + tid) * 4;
            *(float4*)&u2[off] = *(const float4*)(up2 + off);
        }
    }

    // --- epilogue constants ---
    const int b1l = tid >> 4;                  // P1 local b (0..15)
    const int b1  = gb0 + b1l;
    const int n1  = cl * 32 + (tid & 15) * 2;  // P1 n (0..1022)
    const float2 ub1 = *(const float2*)&g_ubias[n1];
    const int o1c = b1l * 16 + ((tid & 15) ^ ((b1l >> 2) << 1));
    const int o2  = tid & 127;
    const int b2l = o2 >> 3;
    const int b2  = gb0 + b2l;
    const int n2  = cl * 16 + (o2 & 7) * 2;
    const float2 ub2 = *(const float2*)&g_ubias[1024 + n2];
    const int o2c = b2l * 8 + ((o2 & 7) ^ ((b2l >> 1) & 3));

    // --- compute-lane constants ---
    const int bg  = lane >> 3;   // P1: 4 b-groups of 4 rows
    const int ng  = lane & 7;    // P1: 8 n-groups of 4 cols
    const int bg2 = lane >> 2;   // P2: 8 b-groups of 2 rows
    const int ng2 = lane & 3;    // P2: 4 n-groups of 4 cols
    const int lb  = tid >> 4;    // tile-load row (0..15)
    const int co  = tid & 15;    // tile-load chunk lane

    unsigned bar = 0;

    for (int s = 0; s < S_LEN; s++) {
        const float* hprev = (s == 0) ? h0 : (out + (s - 1) * (B_DIM * 512));

        // --- prefetch epilogue operands ---
        float2 pre1 = *(const float2*)&g_pre[(s * 64 + b1) * 1536 + n1];
        float2 pre2;
        if (tid < 128)
            pre2 = *(const float2*)&g_pre[(s * 64 + b2) * 1536 + 1024 + n2];

        // --- load h tile (group's 16 rows) ---
        {
            const float4* hp4 = (const float4*)(hprev + (gb0 + lb) * 512);
#pragma unroll
            for (int q = 0; q < 8; q++) {
                int c = q * 16 + co;
                hs4[lb * 128 + swz2(lb, c)] = hp4[c];
            }
        }
        __syncthreads();

        // ================= Phase 1: zr = sigmoid(pre + h@Uzr^T + ub) ========
        {
            u64 acc[4][2];
#pragma unroll
            for (int i = 0; i < 4; i++) { acc[i][0] = 0ull; acc[i][1] = 0ull; }
            const float4* hr0 = hs4 + (bg * 4 + 0) * 128;
            const float4* hr1 = hs4 + (bg * 4 + 1) * 128;
            const float4* hr2 = hs4 + (bg * 4 + 2) * 128;
            const float4* hr3 = hs4 + (bg * 4 + 3) * 128;
            const int m0 = bg * 2, m1 = (bg * 2) ^ 4;
            const int m2 = bg * 2 + 1, m3 = (bg * 2 + 1) ^ 4;
            const float* upc = us + ng * 4;
#pragma unroll
            for (int cc = 0; cc < 16; cc++) {
                int cb = w * 16 + cc;
                int cx = cb ^ w;
                float4 hv0 = hr0[cx ^ m0];
                float4 hv1 = hr1[cx ^ m1];
                float4 hv2 = hr2[cx ^ m2];
                float4 hv3 = hr3[cx ^ m3];
                const float* ub = upc + cb * 128;
                ulonglong2 uu0 = *(const ulonglong2*)(ub);
                ulonglong2 uu1 = *(const ulonglong2*)(ub + 32);
                ulonglong2 uu2 = *(const ulonglong2*)(ub + 64);
                ulonglong2 uu3 = *(const ulonglong2*)(ub + 96);
                u64 d;
                d = dupf(hv0.x); fma2(acc[0][0], d, uu0.x); fma2(acc[0][1], d, uu0.y);
                d = dupf(hv1.x); fma2(acc[1][0], d, uu0.x); fma2(acc[1][1], d, uu0.y);
                d = dupf(hv2.x); fma2(acc[2][0], d, uu0.x); fma2(acc[2][1], d, uu0.y);
                d = dupf(hv3.x); fma2(acc[3][0], d, uu0.x); fma2(acc[3][1], d, uu0.y);
                d = dupf(hv0.y); fma2(acc[0][0], d, uu1.x); fma2(acc[0][1], d, uu1.y);
                d = dupf(hv1.y); fma2(acc[1][0], d, uu1.x); fma2(acc[1][1], d, uu1.y);
                d = dupf(hv2.y); fma2(acc[2][0], d, uu1.x); fma2(acc[2][1], d, uu1.y);
                d = dupf(hv3.y); fma2(acc[3][0], d, uu1.x); fma2(acc[3][1], d, uu1.y);
                d = dupf(hv0.z); fma2(acc[0][0], d, uu2.x); fma2(acc[0][1], d, uu2.y);
                d = dupf(hv1.z); fma2(acc[1][0], d, uu2.x); fma2(acc[1][1], d, uu2.y);
                d = dupf(hv2.z); fma2(acc[2][0], d, uu2.x); fma2(acc[2][1], d, uu2.y);
                d = dupf(hv3.z); fma2(acc[3][0], d, uu2.x); fma2(acc[3][1], d, uu2.y);
                d = dupf(hv0.w); fma2(acc[0][0], d, uu3.x); fma2(acc[0][1], d, uu3.y);
                d = dupf(hv1.w); fma2(acc[1][0], d, uu3.x); fma2(acc[1][1], d, uu3.y);
                d = dupf(hv2.w); fma2(acc[2][0], d, uu3.x); fma2(acc[2][1], d, uu3.y);
                d = dupf(hv3.w); fma2(acc[3][0], d, uu3.x); fma2(acc[3][1], d, uu3.y);
            }
            int rbase = w * 256;
#pragma unroll
            for (int i = 0; i < 4; i++) {
                int bl = bg * 4 + i;
                red[rbase + bl * 16 + ((ng * 2)     ^ (bg << 1))] = acc[i][0];
                red[rbase + bl * 16 + ((ng * 2 + 1) ^ (bg << 1))] = acc[i][1];
            }
            __syncthreads();
            {
                u64 ssum = red[o1c];
#pragma unroll
                for (int p = 1; p < 8; p++) ssum = add2(ssum, red[p * 256 + o1c]);
                float v0s, v1s; unpk(ssum, v0s, v1s);
                float a0 = pre1.x + v0s + ub1.x;
                float a1 = pre1.y + v1s + ub1.y;
                float v0 = 1.f / (1.f + __expf(-a0));
                float v1 = 1.f / (1.f + __expf(-a1));
                if (cl < 16) {
                    *(float2*)&g_z[b1 * 512 + n1] = make_float2(v0, v1);
                } else {
                    int j = n1 - 512;
                    int c = j >> 2;
                    const float* ch = (const float*)&hs4[b1l * 128 + swz2(b1l, c)];
                    *(float2*)&g_rh[b1 * 512 + j] =
                        make_float2(v0 * ch[j & 3], v1 * ch[(j & 3) + 1]);
                }
            }
        }
        group_sync(gbase, ++bar);

        // --- prefetch z for P2 epilogue ---
        float2 zf;
        if (tid < 128) zf = *(const float2*)&g_z[b2 * 512 + n2];

        // --- load rh tile ---
        {
            const float4* rp4 = (const float4*)(g_rh + (gb0 + lb) * 512);
#pragma unroll
            for (int q = 0; q < 8; q++) {
                int c = q * 16 + co;
                rs4[lb * 128 + swz2(lb, c)] = rp4[c];
            }
        }
        __syncthreads();

        // ================= Phase 2: h~ = tanh(pre + rh@Uh^T + ub) ===========
        {
            u64 acc[2][2];
            acc[0][0] = acc[0][1] = acc[1][0] = acc[1][1] = 0ull;
            const float4* rr0 = rs4 + (bg2 * 2 + 0) * 128;
            const float4* rr1 = rs4 + (bg2 * 2 + 1) * 128;
            const int q0 = bg2, q1 = bg2 ^ 4;
            const float* upc = u2 + ng2 * 4;
#pragma unroll
            for (int cc = 0; cc < 16; cc++) {
                int cb = w * 16 + cc;
                int cx = cb ^ w;
                float4 rv0 = rr0[cx ^ q0];
                float4 rv1 = rr1[cx ^ q1];
                const float* ub = upc + cb * 64;
                ulonglong2 uu0 = *(const ulonglong2*)(ub);
                ulonglong2 uu1 = *(const ulonglong2*)(ub + 16);
                ulonglong2 uu2 = *(const ulonglong2*)(ub + 32);
                ulonglong2 uu3 = *(const ulonglong2*)(ub + 48);
                u64 d;
                d = dupf(rv0.x); fma2(acc[0][0], d, uu0.x); fma2(acc[0][1], d, uu0.y);
                d = dupf(rv1.x); fma2(acc[1][0], d, uu0.x); fma2(acc[1][1], d, uu0.y);
                d = dupf(rv0.y); fma2(acc[0][0], d, uu1.x); fma2(acc[0][1], d, uu1.y);
                d = dupf(rv1.y); fma2(acc[1][0], d, uu1.x); fma2(acc[1][1], d, uu1.y);
                d = dupf(rv0.z); fma2(acc[0][0], d, uu2.x); fma2(acc[0][1], d, uu2.y);
                d = dupf(rv1.z); fma2(acc[1][0], d, uu2.x); fma2(acc[1][1], d, uu2.y);
                d = dupf(rv0.w); fma2(acc[0][0], d, uu3.x); fma2(acc[0][1], d, uu3.y);
                d = dupf(rv1.w); fma2(acc[1][0], d, uu3.x); fma2(acc[1][1], d, uu3.y);
            }
            int rbase = w * 128;
#pragma unroll
            for (int i = 0; i < 2; i++) {
                int bl = bg2 * 2 + i;
                red[rbase + bl * 8 + ((ng2 * 2)     ^ (bg2 & 3))] = acc[i][0];
                red[rbase + bl * 8 + ((ng2 * 2 + 1) ^ (bg2 & 3))] = acc[i][1];
            }
            __syncthreads();
            if (tid < 128) {
                u64 ssum = red[o2c];
#pragma unroll
                for (int p = 1; p < 8; p++) ssum = add2(ssum, red[p * 128 + o2c]);
                float v0s, v1s; unpk(ssum, v0s, v1s);
                int c = n2 >> 2;
                const float* ch = (const float*)&hs4[b2l * 128 + swz2(b2l, c)];
                float hp0 = ch[n2 & 3], hp1 = ch[(n2 & 3) + 1];
                float a0 = pre2.x + v0s + ub2.x;
                float a1 = pre2.y + v1s + ub2.y;
                float e0 = __expf(2.f * a0), e1 = __expf(2.f * a1);
                float th0 = 1.f - 2.f / (e0 + 1.f);
                float th1 = 1.f - 2.f / (e1 + 1.f);
                float hn0 = hp0 + zf.x * (th0 - hp0);
                float hn1 = hp1 + zf.y * (th1 - hp1);
                float2 o = make_float2(hn0, hn1);
                *(float2*)&out[s * (B_DIM * 512) + b2 * 512 + n2] = o;
                if (s == S_LEN - 1)
                    *(float2*)&out[S_LEN * (B_DIM * 512) + b2 * 512 + n2] = o;
            }
        }
        group_sync(gbase, ++bar);
    }
}

// ---------------- launch ----------------------------------------------------
extern "C" void kernel_launch(void* const* d_in, const int* in_sizes, int n_in,
                              void* d_out, int out_size) {
    (void)in_sizes; (void)n_in; (void)out_size;
    const float* x    = (const float*)d_in[0];
    const float* h0   = (const float*)d_in[1];
    const float* Wz_w = (const float*)d_in[2];
    const float* Wz_b = (const float*)d_in[3];
    const float* Uz_w = (const float*)d_in[4];
    const float* Uz_b = (const float*)d_in[5];
    const float* Wr_w = (const float*)d_in[6];
    const float* Wr_b = (const float*)d_in[7];
    const float* Ur_w = (const float*)d_in[8];
    const float* Ur_b = (const float*)d_in[9];
    const float* Wh_w = (const float*)d_in[10];
    const float* Wh_b = (const float*)d_in[11];
    const float* Uh_w = (const float*)d_in[12];
    const float* Uh_b = (const float*)d_in[13];
    float* out = (float*)d_out;

    static int smem_set = 0;
    if (!smem_set) {
        cudaFuncSetAttribute(gru_scan, cudaFuncAttributeMaxDynamicSharedMemorySize,
                             180224);
        smem_set = 1;
    }

    pack_kernel<<<256, 256>>>(Wz_w, Wz_b, Uz_w, Uz_b,
                              Wr_w, Wr_b, Ur_w, Ur_b,
                              Wh_w, Wh_b, Uh_w, Uh_b);
    input_gemm<<<dim3(24, 512), 256>>>(x);
    gru_scan<<<NBLK, 256, 180224>>>(h0, out);
}

// round 9
// speedup vs baseline: 1.6742x; 1.0212x over previous
#include <cuda_runtime.h>
#include <math.h>

#define S_LEN 1024
#define B_DIM 64
#define NBLK  128
#define GRP_CTAS 32

typedef unsigned long long u64;

// ---------------- f32x2 helpers (sm_100+) -----------------------------------
__device__ __forceinline__ u64 dupf(float x) {
    u64 r; unsigned xi = __float_as_uint(x);
    asm("mov.b64 %0, {%1, %1};" : "=l"(r) : "r"(xi));
    return r;
}
__device__ __forceinline__ void fma2(u64& d, u64 a, u64 b) {
    asm("fma.rn.f32x2 %0, %1, %2, %0;" : "+l"(d) : "l"(a), "l"(b));
}
__device__ __forceinline__ u64 add2(u64 a, u64 b) {
    u64 d; asm("add.rn.f32x2 %0, %1, %2;" : "=l"(d) : "l"(a), "l"(b));
    return d;
}
__device__ __forceinline__ void unpk(u64 p, float& lo, float& hi) {
    unsigned a, b;
    asm("mov.b64 {%0, %1}, %2;" : "=r"(a), "=r"(b) : "l"(p));
    lo = __uint_as_float(a); hi = __uint_as_float(b);
}

// swizzled chunk column for 16-row tiles
__device__ __forceinline__ int swz2(int b, int c) {
    return c ^ ((b >> 1) & 7) ^ ((c >> 4) & 7) ^ ((b & 1) << 2);
}

// ---------------- device scratch --------------------------------------------
__device__ float g_pre[S_LEN * B_DIM * 1536];   // xz|xr|xh preactivations
__device__ float g_WT[512 * 1536];              // [k][n] input weights (k-major)
__device__ float g_Uzrp[32 * 512 * 32];         // packed [cl][k][32n] zr weights
__device__ float g_Uhp[32 * 512 * 16];          // packed [cl][k][16n] h weights
__device__ float g_wbias[1536];
__device__ float g_ubias[1536];
__device__ float g_z[B_DIM * 512];
__device__ float g_rh[B_DIM * 512];
__device__ unsigned g_flags[NBLK * 32];         // per-CTA barrier flags, 128B stride

// ---------------- pack + flag reset -----------------------------------------
__global__ void pack_kernel(const float* Wz, const float* bz, const float* Uz, const float* ubz,
                            const float* Wr, const float* br, const float* Ur, const float* ubr,
                            const float* Wh, const float* bh, const float* Uh, const float* ubh) {
    int stride = gridDim.x * blockDim.x;
    int t = blockIdx.x * blockDim.x + threadIdx.x;
    for (int idx = t; idx < NBLK * 32; idx += stride) g_flags[idx] = 0u;
    for (int idx = t; idx < 512 * 1536; idx += stride) {
        int k = idx / 1536, n = idx % 1536;
        const float* W = (n < 512) ? Wz : (n < 1024 ? Wr : Wh);
        g_WT[idx] = W[(n & 511) * 512 + k];
    }
    for (int idx = t; idx < 32 * 512 * 32; idx += stride) {
        int cl = idx >> 14, k = (idx >> 5) & 511, nn = idx & 31;
        int n = cl * 32 + nn;
        g_Uzrp[idx] = (n < 512) ? Uz[n * 512 + k] : Ur[(n - 512) * 512 + k];
    }
    for (int idx = t; idx < 32 * 512 * 16; idx += stride) {
        int cl = idx >> 13, k = (idx >> 4) & 511, nn = idx & 15;
        g_Uhp[idx] = Uh[(cl * 16 + nn) * 512 + k];
    }
    for (int idx = t; idx < 1536; idx += stride) {
        int n = idx & 511;
        g_wbias[idx] = (idx < 512) ? bz[n] : (idx < 1024 ? br[n] : bh[n]);
        g_ubias[idx] = (idx < 512) ? ubz[n] : (idx < 1024 ? ubr[n] : ubh[n]);
    }
}

// ---------------- input projection GEMM (f32x2, double-buffered) ------------
// C[65536,1536] = X[65536,512] * WT[512,1536]; BM=128,BN=64,BK=16, 8x4/thread.
__global__ __launch_bounds__(256) void input_gemm(const float* __restrict__ x) {
    __shared__ float As[2][16 * 132];
    __shared__ float Bs[2][16 * 64];
    int tid = threadIdx.x;
    int tx = tid & 15, ty = tid >> 4;
    int m0 = blockIdx.y * 128;
    int n0 = blockIdx.x * 64;

    const int fA0 = tid,       mA0 = fA0 >> 2, kqA0 = fA0 & 3;
    const int fA1 = 256 + tid, mA1 = fA1 >> 2, kqA1 = fA1 & 3;
    const int kB  = tid >> 4,  nqB = tid & 15;
    const float* xA0 = x + (m0 + mA0) * 512 + kqA0 * 4;
    const float* xA1 = x + (m0 + mA1) * 512 + kqA1 * 4;
    const float* wB  = g_WT + kB * 1536 + n0 + nqB * 4;

    u64 acc[8][2];
#pragma unroll
    for (int i = 0; i < 8; i++) { acc[i][0] = 0ull; acc[i][1] = 0ull; }

    // prologue: tile 0 -> buf 0
    {
        float4 a0 = *(const float4*)(xA0);
        float4 a1 = *(const float4*)(xA1);
        float4 b0 = *(const float4*)(wB);
        As[0][(kqA0 * 4 + 0) * 132 + mA0] = a0.x;
        As[0][(kqA0 * 4 + 1) * 132 + mA0] = a0.y;
        As[0][(kqA0 * 4 + 2) * 132 + mA0] = a0.z;
        As[0][(kqA0 * 4 + 3) * 132 + mA0] = a0.w;
        As[0][(kqA1 * 4 + 0) * 132 + mA1] = a1.x;
        As[0][(kqA1 * 4 + 1) * 132 + mA1] = a1.y;
        As[0][(kqA1 * 4 + 2) * 132 + mA1] = a1.z;
        As[0][(kqA1 * 4 + 3) * 132 + mA1] = a1.w;
        *(float4*)&Bs[0][kB * 64 + nqB * 4] = b0;
    }
    __syncthreads();

    for (int kt = 0; kt < 32; kt++) {
        int cur = kt & 1;
        float4 a0n, a1n, b0n;
        if (kt < 31) {                       // issue next-tile loads early
            int k0 = (kt + 1) * 16;
            a0n = *(const float4*)(xA0 + k0);
            a1n = *(const float4*)(xA1 + k0);
            b0n = *(const float4*)(wB + (unsigned)k0 * 1536);
        }
        const float* Ac = As[cur];
        const float* Bc = Bs[cur];
#pragma unroll
        for (int kk = 0; kk < 16; kk++) {
            float4 a0 = *(const float4*)&Ac[kk * 132 + ty * 8];
            float4 a1 = *(const float4*)&Ac[kk * 132 + ty * 8 + 4];
            ulonglong2 bb = *(const ulonglong2*)&Bc[kk * 64 + tx * 4];
            u64 d0 = dupf(a0.x), d1 = dupf(a0.y), d2 = dupf(a0.z), d3 = dupf(a0.w);
            u64 d4 = dupf(a1.x), d5 = dupf(a1.y), d6 = dupf(a1.z), d7 = dupf(a1.w);
            fma2(acc[0][0], d0, bb.x); fma2(acc[0][1], d0, bb.y);
            fma2(acc[1][0], d1, bb.x); fma2(acc[1][1], d1, bb.y);
            fma2(acc[2][0], d2, bb.x); fma2(acc[2][1], d2, bb.y);
            fma2(acc[3][0], d3, bb.x); fma2(acc[3][1], d3, bb.y);
            fma2(acc[4][0], d4, bb.x); fma2(acc[4][1], d4, bb.y);
            fma2(acc[5][0], d5, bb.x); fma2(acc[5][1], d5, bb.y);
            fma2(acc[6][0], d6, bb.x); fma2(acc[6][1], d6, bb.y);
            fma2(acc[7][0], d7, bb.x); fma2(acc[7][1], d7, bb.y);
        }
        if (kt < 31) {
            int nxt = cur ^ 1;
            As[nxt][(kqA0 * 4 + 0) * 132 + mA0] = a0n.x;
            As[nxt][(kqA0 * 4 + 1) * 132 + mA0] = a0n.y;
            As[nxt][(kqA0 * 4 + 2) * 132 + mA0] = a0n.z;
            As[nxt][(kqA0 * 4 + 3) * 132 + mA0] = a0n.w;
            As[nxt][(kqA1 * 4 + 0) * 132 + mA1] = a1n.x;
            As[nxt][(kqA1 * 4 + 1) * 132 + mA1] = a1n.y;
            As[nxt][(kqA1 * 4 + 2) * 132 + mA1] = a1n.z;
            As[nxt][(kqA1 * 4 + 3) * 132 + mA1] = a1n.w;
            *(float4*)&Bs[nxt][kB * 64 + nqB * 4] = b0n;
            __syncthreads();
        }
    }
#pragma unroll
    for (int i = 0; i < 8; i++) {
        int m = m0 + ty * 8 + i;
        int n = n0 + tx * 4;
        float4 o;
        float v0, v1, v2, v3;
        unpk(acc[i][0], v0, v1);
        unpk(acc[i][1], v2, v3);
        o.x = v0 + g_wbias[n + 0];
        o.y = v1 + g_wbias[n + 1];
        o.z = v2 + g_wbias[n + 2];
        o.w = v3 + g_wbias[n + 3];
        *(float4*)&g_pre[m * 1536 + n] = o;
    }
}

// ---------------- per-group barrier (32 CTAs) -------------------------------
__device__ __forceinline__ void group_sync(int gbase, unsigned target) {
    __syncthreads();
    if (threadIdx.x == 0) {
        asm volatile("st.release.gpu.u32 [%0], %1;"
                     :: "l"(&g_flags[blockIdx.x * 32]), "r"(target) : "memory");
    }
    if (threadIdx.x < GRP_CTAS) {
        unsigned v;
        const unsigned* fp = &g_flags[(gbase + threadIdx.x) * 32];
        do {
            asm volatile("ld.acquire.gpu.u32 %0, [%1];"
                         : "=r"(v) : "l"(fp) : "memory");
        } while (v < target);
    }
    __syncthreads();
}

// ---------------- persistent GRU scan: 4 independent groups -----------------
__global__ __launch_bounds__(256, 1) void gru_scan(const float* __restrict__ h0,
                                                   float* out) {
    extern __shared__ float smem[];
    float4* hs4 = (float4*)smem;                // [16][128] chunks swizzled, 32KB
    float4* rs4 = hs4 + 2048;                   // [16][128] chunks swizzled, 32KB
    float*  us  = smem + 16384;                 // [512][32]  64KB zr weights
    float*  u2  = smem + 32768;                 // [512][16]  32KB h  weights
    u64*    red = (u64*)(smem + 40960);         // 2048 u64   16KB

    const int tid  = threadIdx.x;
    const int cta  = blockIdx.x;
    const int w    = tid >> 5;
    const int lane = tid & 31;
    const int g    = cta >> 5;
    const int cl   = cta & 31;
    const int gbase = cta & ~(GRP_CTAS - 1);
    const int gb0  = g * 16;                    // group batch base

    // --- resident weights ---
    {
        const float* up1 = g_Uzrp + cl * 16384;
#pragma unroll
        for (int i = 0; i < 16; i++) {
            int off = (i * 256 + tid) * 4;
            *(float4*)&us[off] = *(const float4*)(up1 + off);
        }
        const float* up2 = g_Uhp + cl * 8192;
#pragma unroll
        for (int i = 0; i < 8; i++) {
            int off = (i * 256 + tid) * 4;
            *(float4*)&u2[off] = *(const float4*)(up2 + off);
        }
    }

    // --- epilogue constants ---
    const int b1l = tid >> 4;                  // P1 local b (0..15)
    const int b1  = gb0 + b1l;
    const int n1  = cl * 32 + (tid & 15) * 2;  // P1 n (0..1022)
    const float2 ub1 = *(const float2*)&g_ubias[n1];
    const int o1c = b1l * 16 + ((tid & 15) ^ ((b1l >> 2) << 1));
    const int o2  = tid & 127;
    const int b2l = o2 >> 3;
    const int b2  = gb0 + b2l;
    const int n2  = cl * 16 + (o2 & 7) * 2;
    const float2 ub2 = *(const float2*)&g_ubias[1024 + n2];
    const int o2c = b2l * 8 + ((o2 & 7) ^ ((b2l >> 1) & 3));

    // --- compute-lane constants ---
    const int bg  = lane >> 3;   // P1: 4 b-groups of 4 rows
    const int ng  = lane & 7;    // P1: 8 n-groups of 4 cols
    const int bg2 = lane >> 2;   // P2: 8 b-groups of 2 rows
    const int ng2 = lane & 3;    // P2: 4 n-groups of 4 cols
    const int lb  = tid >> 4;    // tile-load row (0..15)
    const int co  = tid & 15;    // tile-load chunk lane

    unsigned bar = 0;

    for (int s = 0; s < S_LEN; s++) {
        const float* hprev = (s == 0) ? h0 : (out + (s - 1) * (B_DIM * 512));

        // --- prefetch epilogue operands ---
        float2 pre1 = *(const float2*)&g_pre[(s * 64 + b1) * 1536 + n1];
        float2 pre2;
        if (tid < 128)
            pre2 = *(const float2*)&g_pre[(s * 64 + b2) * 1536 + 1024 + n2];

        // --- load h tile (group's 16 rows) ---
        {
            const float4* hp4 = (const float4*)(hprev + (gb0 + lb) * 512);
#pragma unroll
            for (int q = 0; q < 8; q++) {
                int c = q * 16 + co;
                hs4[lb * 128 + swz2(lb, c)] = hp4[c];
            }
        }
        __syncthreads();

        // ================= Phase 1: zr = sigmoid(pre + h@Uzr^T + ub) ========
        {
            u64 acc[4][2];
#pragma unroll
            for (int i = 0; i < 4; i++) { acc[i][0] = 0ull; acc[i][1] = 0ull; }
            const float4* hr0 = hs4 + (bg * 4 + 0) * 128;
            const float4* hr1 = hs4 + (bg * 4 + 1) * 128;
            const float4* hr2 = hs4 + (bg * 4 + 2) * 128;
            const float4* hr3 = hs4 + (bg * 4 + 3) * 128;
            const int m0 = bg * 2, m1 = (bg * 2) ^ 4;
            const int m2 = bg * 2 + 1, m3 = (bg * 2 + 1) ^ 4;
            const float* upc = us + ng * 4;
#pragma unroll
            for (int cc = 0; cc < 16; cc++) {
                int cb = w * 16 + cc;
                int cx = cb ^ w;
                float4 hv0 = hr0[cx ^ m0];
                float4 hv1 = hr1[cx ^ m1];
                float4 hv2 = hr2[cx ^ m2];
                float4 hv3 = hr3[cx ^ m3];
                const float* ub = upc + cb * 128;
                ulonglong2 uu0 = *(const ulonglong2*)(ub);
                ulonglong2 uu1 = *(const ulonglong2*)(ub + 32);
                ulonglong2 uu2 = *(const ulonglong2*)(ub + 64);
                ulonglong2 uu3 = *(const ulonglong2*)(ub + 96);
                u64 d;
                d = dupf(hv0.x); fma2(acc[0][0], d, uu0.x); fma2(acc[0][1], d, uu0.y);
                d = dupf(hv1.x); fma2(acc[1][0], d, uu0.x); fma2(acc[1][1], d, uu0.y);
                d = dupf(hv2.x); fma2(acc[2][0], d, uu0.x); fma2(acc[2][1], d, uu0.y);
                d = dupf(hv3.x); fma2(acc[3][0], d, uu0.x); fma2(acc[3][1], d, uu0.y);
                d = dupf(hv0.y); fma2(acc[0][0], d, uu1.x); fma2(acc[0][1], d, uu1.y);
                d = dupf(hv1.y); fma2(acc[1][0], d, uu1.x); fma2(acc[1][1], d, uu1.y);
                d = dupf(hv2.y); fma2(acc[2][0], d, uu1.x); fma2(acc[2][1], d, uu1.y);
                d = dupf(hv3.y); fma2(acc[3][0], d, uu1.x); fma2(acc[3][1], d, uu1.y);
                d = dupf(hv0.z); fma2(acc[0][0], d, uu2.x); fma2(acc[0][1], d, uu2.y);
                d = dupf(hv1.z); fma2(acc[1][0], d, uu2.x); fma2(acc[1][1], d, uu2.y);
                d = dupf(hv2.z); fma2(acc[2][0], d, uu2.x); fma2(acc[2][1], d, uu2.y);
                d = dupf(hv3.z); fma2(acc[3][0], d, uu2.x); fma2(acc[3][1], d, uu2.y);
                d = dupf(hv0.w); fma2(acc[0][0], d, uu3.x); fma2(acc[0][1], d, uu3.y);
                d = dupf(hv1.w); fma2(acc[1][0], d, uu3.x); fma2(acc[1][1], d, uu3.y);
                d = dupf(hv2.w); fma2(acc[2][0], d, uu3.x); fma2(acc[2][1], d, uu3.y);
                d = dupf(hv3.w); fma2(acc[3][0], d, uu3.x); fma2(acc[3][1], d, uu3.y);
            }
            int rbase = w * 256;
#pragma unroll
            for (int i = 0; i < 4; i++) {
                int bl = bg * 4 + i;
                red[rbase + bl * 16 + ((ng * 2)     ^ (bg << 1))] = acc[i][0];
                red[rbase + bl * 16 + ((ng * 2 + 1) ^ (bg << 1))] = acc[i][1];
            }
            __syncthreads();
            {
                u64 ssum = red[o1c];
#pragma unroll
                for (int p = 1; p < 8; p++) ssum = add2(ssum, red[p * 256 + o1c]);
                float v0s, v1s; unpk(ssum, v0s, v1s);
                float a0 = pre1.x + v0s + ub1.x;
                float a1 = pre1.y + v1s + ub1.y;
                float v0 = 1.f / (1.f + __expf(-a0));
                float v1 = 1.f / (1.f + __expf(-a1));
                if (cl < 16) {
                    *(float2*)&g_z[b1 * 512 + n1] = make_float2(v0, v1);
                } else {
                    int j = n1 - 512;
                    int c = j >> 2;
                    const float* ch = (const float*)&hs4[b1l * 128 + swz2(b1l, c)];
                    *(float2*)&g_rh[b1 * 512 + j] =
                        make_float2(v0 * ch[j & 3], v1 * ch[(j & 3) + 1]);
                }
            }
        }
        group_sync(gbase, ++bar);

        // --- prefetch z for P2 epilogue ---
        float2 zf;
        if (tid < 128) zf = *(const float2*)&g_z[b2 * 512 + n2];

        // --- load rh tile ---
        {
            const float4* rp4 = (const float4*)(g_rh + (gb0 + lb) * 512);
#pragma unroll
            for (int q = 0; q < 8; q++) {
                int c = q * 16 + co;
                rs4[lb * 128 + swz2(lb, c)] = rp4[c];
            }
        }
        __syncthreads();

        // ================= Phase 2: h~ = tanh(pre + rh@Uh^T + ub) ===========
        {
            u64 acc[2][2];
            acc[0][0] = acc[0][1] = acc[1][0] = acc[1][1] = 0ull;
            const float4* rr0 = rs4 + (bg2 * 2 + 0) * 128;
            const float4* rr1 = rs4 + (bg2 * 2 + 1) * 128;
            const int q0 = bg2, q1 = bg2 ^ 4;
            const float* upc = u2 + ng2 * 4;
#pragma unroll
            for (int cc = 0; cc < 16; cc++) {
                int cb = w * 16 + cc;
                int cx = cb ^ w;
                float4 rv0 = rr0[cx ^ q0];
                float4 rv1 = rr1[cx ^ q1];
                const float* ub = upc + cb * 64;
                ulonglong2 uu0 = *(const ulonglong2*)(ub);
                ulonglong2 uu1 = *(const ulonglong2*)(ub + 16);
                ulonglong2 uu2 = *(const ulonglong2*)(ub + 32);
                ulonglong2 uu3 = *(const ulonglong2*)(ub + 48);
                u64 d;
                d = dupf(rv0.x); fma2(acc[0][0], d, uu0.x); fma2(acc[0][1], d, uu0.y);
                d = dupf(rv1.x); fma2(acc[1][0], d, uu0.x); fma2(acc[1][1], d, uu0.y);
                d = dupf(rv0.y); fma2(acc[0][0], d, uu1.x); fma2(acc[0][1], d, uu1.y);
                d = dupf(rv1.y); fma2(acc[1][0], d, uu1.x); fma2(acc[1][1], d, uu1.y);
                d = dupf(rv0.z); fma2(acc[0][0], d, uu2.x); fma2(acc[0][1], d, uu2.y);
                d = dupf(rv1.z); fma2(acc[1][0], d, uu2.x); fma2(acc[1][1], d, uu2.y);
                d = dupf(rv0.w); fma2(acc[0][0], d, uu3.x); fma2(acc[0][1], d, uu3.y);
                d = dupf(rv1.w); fma2(acc[1][0], d, uu3.x); fma2(acc[1][1], d, uu3.y);
            }
            int rbase = w * 128;
#pragma unroll
            for (int i = 0; i < 2; i++) {
                int bl = bg2 * 2 + i;
                red[rbase + bl * 8 + ((ng2 * 2)     ^ (bg2 & 3))] = acc[i][0];
                red[rbase + bl * 8 + ((ng2 * 2 + 1) ^ (bg2 & 3))] = acc[i][1];
            }
            __syncthreads();
            if (tid < 128) {
                u64 ssum = red[o2c];
#pragma unroll
                for (int p = 1; p < 8; p++) ssum = add2(ssum, red[p * 128 + o2c]);
                float v0s, v1s; unpk(ssum, v0s, v1s);
                int c = n2 >> 2;
                const float* ch = (const float*)&hs4[b2l * 128 + swz2(b2l, c)];
                float hp0 = ch[n2 & 3], hp1 = ch[(n2 & 3) + 1];
                float a0 = pre2.x + v0s + ub2.x;
                float a1 = pre2.y + v1s + ub2.y;
                float e0 = __expf(2.f * a0), e1 = __expf(2.f * a1);
                float th0 = 1.f - 2.f / (e0 + 1.f);
                float th1 = 1.f - 2.f / (e1 + 1.f);
                float hn0 = hp0 + zf.x * (th0 - hp0);
                float hn1 = hp1 + zf.y * (th1 - hp1);
                float2 o = make_float2(hn0, hn1);
                *(float2*)&out[s * (B_DIM * 512) + b2 * 512 + n2] = o;
                if (s == S_LEN - 1)
                    *(float2*)&out[S_LEN * (B_DIM * 512) + b2 * 512 + n2] = o;
            }
        }
        group_sync(gbase, ++bar);
    }
}

// ---------------- launch ----------------------------------------------------
extern "C" void kernel_launch(void* const* d_in, const int* in_sizes, int n_in,
                              void* d_out, int out_size) {
    (void)in_sizes; (void)n_in; (void)out_size;
    const float* x    = (const float*)d_in[0];
    const float* h0   = (const float*)d_in[1];
    const float* Wz_w = (const float*)d_in[2];
    const float* Wz_b = (const float*)d_in[3];
    const float* Uz_w = (const float*)d_in[4];
    const float* Uz_b = (const float*)d_in[5];
    const float* Wr_w = (const float*)d_in[6];
    const float* Wr_b = (const float*)d_in[7];
    const float* Ur_w = (const float*)d_in[8];
    const float* Ur_b = (const float*)d_in[9];
    const float* Wh_w = (const float*)d_in[10];
    const float* Wh_b = (const float*)d_in[11];
    const float* Uh_w = (const float*)d_in[12];
    const float* Uh_b = (const float*)d_in[13];
    float* out = (float*)d_out;

    static int smem_set = 0;
    if (!smem_set) {
        cudaFuncSetAttribute(gru_scan, cudaFuncAttributeMaxDynamicSharedMemorySize,
                             180224);
        smem_set = 1;
    }

    pack_kernel<<<256, 256>>>(Wz_w, Wz_b, Uz_w, Uz_b,
                              Wr_w, Wr_b, Ur_w, Ur_b,
                              Wh_w, Wh_b, Uh_w, Uh_b);
    input_gemm<<<dim3(24, 512), 256>>>(x);
    gru_scan<<<NBLK, 256, 180224>>>(h0, out);
}

// round 10
// speedup vs baseline: 1.7276x; 1.0319x over previous
#include <cuda_runtime.h>
#include <math.h>

#define S_LEN 1024
#define B_DIM 64
#define NBLK  128
#define GRP_CTAS 32

typedef unsigned long long u64;

// ---------------- f32x2 helpers (sm_100+) -----------------------------------
__device__ __forceinline__ u64 dupf(float x) {
    u64 r; unsigned xi = __float_as_uint(x);
    asm("mov.b64 %0, {%1, %1};" : "=l"(r) : "r"(xi));
    return r;
}
__device__ __forceinline__ void fma2(u64& d, u64 a, u64 b) {
    asm("fma.rn.f32x2 %0, %1, %2, %0;" : "+l"(d) : "l"(a), "l"(b));
}
__device__ __forceinline__ u64 add2(u64 a, u64 b) {
    u64 d; asm("add.rn.f32x2 %0, %1, %2;" : "=l"(d) : "l"(a), "l"(b));
    return d;
}
__device__ __forceinline__ void unpk(u64 p, float& lo, float& hi) {
    unsigned a, b;
    asm("mov.b64 {%0, %1}, %2;" : "=r"(a), "=r"(b) : "l"(p));
    lo = __uint_as_float(a); hi = __uint_as_float(b);
}

// swizzled chunk column for 16-row tiles
__device__ __forceinline__ int swz2(int b, int c) {
    return c ^ ((b >> 1) & 7) ^ ((c >> 4) & 7) ^ ((b & 1) << 2);
}

// ---------------- device scratch --------------------------------------------
__device__ float g_pre[S_LEN * B_DIM * 1536];   // xz|xr|xh preactivations
__device__ float g_WT[512 * 1536];              // [k][n] input weights (k-major)
__device__ float g_Uzrp[32 * 512 * 32];         // packed [cl][k][32n] zr weights
__device__ float g_Uhp[32 * 512 * 16];          // packed [cl][k][16n] h weights
__device__ float g_wbias[1536];
__device__ float g_ubias[1536];
__device__ float g_z[B_DIM * 512];
__device__ float g_rh[B_DIM * 512];
__device__ unsigned g_flags[NBLK * 32];         // per-CTA barrier flags, 128B stride

// ---------------- pack + flag reset -----------------------------------------
__global__ void pack_kernel(const float* Wz, const float* bz, const float* Uz, const float* ubz,
                            const float* Wr, const float* br, const float* Ur, const float* ubr,
                            const float* Wh, const float* bh, const float* Uh, const float* ubh) {
    int stride = gridDim.x * blockDim.x;
    int t = blockIdx.x * blockDim.x + threadIdx.x;
    for (int idx = t; idx < NBLK * 32; idx += stride) g_flags[idx] = 0u;
    for (int idx = t; idx < 512 * 1536; idx += stride) {
        int k = idx / 1536, n = idx % 1536;
        const float* W = (n < 512) ? Wz : (n < 1024 ? Wr : Wh);
        g_WT[idx] = W[(n & 511) * 512 + k];
    }
    for (int idx = t; idx < 32 * 512 * 32; idx += stride) {
        int cl = idx >> 14, k = (idx >> 5) & 511, nn = idx & 31;
        int n = cl * 32 + nn;
        g_Uzrp[idx] = (n < 512) ? Uz[n * 512 + k] : Ur[(n - 512) * 512 + k];
    }
    for (int idx = t; idx < 32 * 512 * 16; idx += stride) {
        int cl = idx >> 13, k = (idx >> 4) & 511, nn = idx & 15;
        g_Uhp[idx] = Uh[(cl * 16 + nn) * 512 + k];
    }
    for (int idx = t; idx < 1536; idx += stride) {
        int n = idx & 511;
        g_wbias[idx] = (idx < 512) ? bz[n] : (idx < 1024 ? br[n] : bh[n]);
        g_ubias[idx] = (idx < 512) ? ubz[n] : (idx < 1024 ? ubr[n] : ubh[n]);
    }
}

// ---------------- input projection GEMM (f32x2, double-buffered) ------------
__global__ __launch_bounds__(256) void input_gemm(const float* __restrict__ x) {
    __shared__ float As[2][16 * 132];
    __shared__ float Bs[2][16 * 64];
    int tid = threadIdx.x;
    int tx = tid & 15, ty = tid >> 4;
    int m0 = blockIdx.y * 128;
    int n0 = blockIdx.x * 64;

    const int fA0 = tid,       mA0 = fA0 >> 2, kqA0 = fA0 & 3;
    const int fA1 = 256 + tid, mA1 = fA1 >> 2, kqA1 = fA1 & 3;
    const int kB  = tid >> 4,  nqB = tid & 15;
    const float* xA0 = x + (m0 + mA0) * 512 + kqA0 * 4;
    const float* xA1 = x + (m0 + mA1) * 512 + kqA1 * 4;
    const float* wB  = g_WT + kB * 1536 + n0 + nqB * 4;

    u64 acc[8][2];
#pragma unroll
    for (int i = 0; i < 8; i++) { acc[i][0] = 0ull; acc[i][1] = 0ull; }

    {
        float4 a0 = *(const float4*)(xA0);
        float4 a1 = *(const float4*)(xA1);
        float4 b0 = *(const float4*)(wB);
        As[0][(kqA0 * 4 + 0) * 132 + mA0] = a0.x;
        As[0][(kqA0 * 4 + 1) * 132 + mA0] = a0.y;
        As[0][(kqA0 * 4 + 2) * 132 + mA0] = a0.z;
        As[0][(kqA0 * 4 + 3) * 132 + mA0] = a0.w;
        As[0][(kqA1 * 4 + 0) * 132 + mA1] = a1.x;
        As[0][(kqA1 * 4 + 1) * 132 + mA1] = a1.y;
        As[0][(kqA1 * 4 + 2) * 132 + mA1] = a1.z;
        As[0][(kqA1 * 4 + 3) * 132 + mA1] = a1.w;
        *(float4*)&Bs[0][kB * 64 + nqB * 4] = b0;
    }
    __syncthreads();

    for (int kt = 0; kt < 32; kt++) {
        int cur = kt & 1;
        float4 a0n, a1n, b0n;
        if (kt < 31) {
            int k0 = (kt + 1) * 16;
            a0n = *(const float4*)(xA0 + k0);
            a1n = *(const float4*)(xA1 + k0);
            b0n = *(const float4*)(wB + (unsigned)k0 * 1536);
        }
        const float* Ac = As[cur];
        const float* Bc = Bs[cur];
#pragma unroll
        for (int kk = 0; kk < 16; kk++) {
            float4 a0 = *(const float4*)&Ac[kk * 132 + ty * 8];
            float4 a1 = *(const float4*)&Ac[kk * 132 + ty * 8 + 4];
            ulonglong2 bb = *(const ulonglong2*)&Bc[kk * 64 + tx * 4];
            u64 d0 = dupf(a0.x), d1 = dupf(a0.y), d2 = dupf(a0.z), d3 = dupf(a0.w);
            u64 d4 = dupf(a1.x), d5 = dupf(a1.y), d6 = dupf(a1.z), d7 = dupf(a1.w);
            fma2(acc[0][0], d0, bb.x); fma2(acc[0][1], d0, bb.y);
            fma2(acc[1][0], d1, bb.x); fma2(acc[1][1], d1, bb.y);
            fma2(acc[2][0], d2, bb.x); fma2(acc[2][1], d2, bb.y);
            fma2(acc[3][0], d3, bb.x); fma2(acc[3][1], d3, bb.y);
            fma2(acc[4][0], d4, bb.x); fma2(acc[4][1], d4, bb.y);
            fma2(acc[5][0], d5, bb.x); fma2(acc[5][1], d5, bb.y);
            fma2(acc[6][0], d6, bb.x); fma2(acc[6][1], d6, bb.y);
            fma2(acc[7][0], d7, bb.x); fma2(acc[7][1], d7, bb.y);
        }
        if (kt < 31) {
            int nxt = cur ^ 1;
            As[nxt][(kqA0 * 4 + 0) * 132 + mA0] = a0n.x;
            As[nxt][(kqA0 * 4 + 1) * 132 + mA0] = a0n.y;
            As[nxt][(kqA0 * 4 + 2) * 132 + mA0] = a0n.z;
            As[nxt][(kqA0 * 4 + 3) * 132 + mA0] = a0n.w;
            As[nxt][(kqA1 * 4 + 0) * 132 + mA1] = a1n.x;
            As[nxt][(kqA1 * 4 + 1) * 132 + mA1] = a1n.y;
            As[nxt][(kqA1 * 4 + 2) * 132 + mA1] = a1n.z;
            As[nxt][(kqA1 * 4 + 3) * 132 + mA1] = a1n.w;
            *(float4*)&Bs[nxt][kB * 64 + nqB * 4] = b0n;
            __syncthreads();
        }
    }
#pragma unroll
    for (int i = 0; i < 8; i++) {
        int m = m0 + ty * 8 + i;
        int n = n0 + tx * 4;
        float4 o;
        float v0, v1, v2, v3;
        unpk(acc[i][0], v0, v1);
        unpk(acc[i][1], v2, v3);
        o.x = v0 + g_wbias[n + 0];
        o.y = v1 + g_wbias[n + 1];
        o.z = v2 + g_wbias[n + 2];
        o.w = v3 + g_wbias[n + 3];
        *(float4*)&g_pre[m * 1536 + n] = o;
    }
}

// ---------------- per-group barrier (32 CTAs) -------------------------------
__device__ __forceinline__ void group_sync(int gbase, unsigned target) {
    __syncthreads();
    if (threadIdx.x == 0) {
        asm volatile("st.release.gpu.u32 [%0], %1;"
                     :: "l"(&g_flags[blockIdx.x * 32]), "r"(target) : "memory");
    }
    if (threadIdx.x < GRP_CTAS) {
        unsigned v;
        const unsigned* fp = &g_flags[(gbase + threadIdx.x) * 32];
        do {
            asm volatile("ld.acquire.gpu.u32 %0, [%1];"
                         : "=r"(v) : "l"(fp) : "memory");
        } while (v < target);
    }
    __syncthreads();
}

// ---------------- persistent GRU scan: 4 independent groups -----------------
__global__ __launch_bounds__(256, 1) void gru_scan(const float* __restrict__ h0,
                                                   float* out) {
    extern __shared__ float smem[];
    float4* hs4 = (float4*)smem;                // [16][128] chunks swizzled, 32KB
    float4* rs4 = hs4 + 2048;                   // [16][128] chunks swizzled, 32KB
    float*  us  = smem + 16384;                 // [512][32]  64KB zr weights
    float*  u2  = smem + 32768;                 // [512][16]  32KB h  weights
    u64*    red = (u64*)(smem + 40960);         // 2048 u64   16KB

    const int tid  = threadIdx.x;
    const int cta  = blockIdx.x;
    const int w    = tid >> 5;
    const int lane = tid & 31;
    const int g    = cta >> 5;
    const int cl   = cta & 31;
    const int gbase = cta & ~(GRP_CTAS - 1);
    const int gb0  = g * 16;                    // group batch base

    // --- resident weights ---
    {
        const float* up1 = g_Uzrp + cl * 16384;
#pragma unroll
        for (int i = 0; i < 16; i++) {
            int off = (i * 256 + tid) * 4;
            *(float4*)&us[off] = *(const float4*)(up1 + off);
        }
        const float* up2 = g_Uhp + cl * 8192;
#pragma unroll
        for (int i = 0; i < 8; i++) {
            int off = (i * 256 + tid) * 4;
            *(float4*)&u2[off] = *(const float4*)(up2 + off);
        }
    }

    // --- epilogue constants ---
    const int b1l = tid >> 4;                  // P1 local b (0..15)
    const int b1  = gb0 + b1l;
    const int n1  = cl * 32 + (tid & 15) * 2;  // P1 n (0..1022)
    const float2 ub1 = *(const float2*)&g_ubias[n1];
    const int o1c = b1l * 16 + ((tid & 15) ^ ((b1l >> 2) << 1));
    const int o2  = tid & 127;
    const int b2l = o2 >> 3;
    const int b2  = gb0 + b2l;
    const int n2  = cl * 16 + (o2 & 7) * 2;
    const float2 ub2 = *(const float2*)&g_ubias[1024 + n2];
    const int o2c = b2l * 8 + ((o2 & 7) ^ ((b2l >> 1) & 3));

    // --- compute-lane constants ---
    const int bg  = lane >> 3;   // P1: 4 b-groups of 4 rows
    const int ng  = lane & 7;    // P1: 8 n-groups of 4 cols
    const int bg2 = lane >> 2;   // P2: 8 b-groups of 2 rows
    const int ng2 = lane & 3;    // P2: 4 n-groups of 4 cols
    // warp-private tile-load lane map: r = q*2 + rh2, c = w*16 + wl
    const int wl  = lane & 15;
    const int rh2 = lane >> 4;
    const int cch = w * 16 + wl;

    unsigned bar = 0;

    // --- prefetch step-0 epilogue operands ---
    float2 pre1 = *(const float2*)&g_pre[b1 * 1536 + n1];
    float2 pre2 = make_float2(0.f, 0.f);
    if (tid < 128)
        pre2 = *(const float2*)&g_pre[b2 * 1536 + 1024 + n2];

    for (int s = 0; s < S_LEN; s++) {
        const float* hprev = (s == 0) ? h0 : (out + (s - 1) * (B_DIM * 512));

        // --- warp-private load of h tile chunks [w*16, w*16+16) ---
        {
            const float4* hp4 = (const float4*)(hprev + gb0 * 512);
#pragma unroll
            for (int q = 0; q < 8; q++) {
                int r = q * 2 + rh2;
                hs4[r * 128 + swz2(r, cch)] = hp4[r * 128 + cch];
            }
            __syncwarp();
        }

        // ================= Phase 1: zr = sigmoid(pre + h@Uzr^T + ub) ========
        {
            u64 acc[4][2];
#pragma unroll
            for (int i = 0; i < 4; i++) { acc[i][0] = 0ull; acc[i][1] = 0ull; }
            const float4* hr0 = hs4 + (bg * 4 + 0) * 128;
            const float4* hr1 = hs4 + (bg * 4 + 1) * 128;
            const float4* hr2 = hs4 + (bg * 4 + 2) * 128;
            const float4* hr3 = hs4 + (bg * 4 + 3) * 128;
            const int m0 = bg * 2, m1 = (bg * 2) ^ 4;
            const int m2 = bg * 2 + 1, m3 = (bg * 2 + 1) ^ 4;
            const float* upc = us + ng * 4;
#pragma unroll
            for (int cc = 0; cc < 16; cc++) {
                int cb = w * 16 + cc;
                int cx = cb ^ w;
                float4 hv0 = hr0[cx ^ m0];
                float4 hv1 = hr1[cx ^ m1];
                float4 hv2 = hr2[cx ^ m2];
                float4 hv3 = hr3[cx ^ m3];
                const float* ub = upc + cb * 128;
                ulonglong2 uu0 = *(const ulonglong2*)(ub);
                ulonglong2 uu1 = *(const ulonglong2*)(ub + 32);
                ulonglong2 uu2 = *(const ulonglong2*)(ub + 64);
                ulonglong2 uu3 = *(const ulonglong2*)(ub + 96);
                u64 d;
                d = dupf(hv0.x); fma2(acc[0][0], d, uu0.x); fma2(acc[0][1], d, uu0.y);
                d = dupf(hv1.x); fma2(acc[1][0], d, uu0.x); fma2(acc[1][1], d, uu0.y);
                d = dupf(hv2.x); fma2(acc[2][0], d, uu0.x); fma2(acc[2][1], d, uu0.y);
                d = dupf(hv3.x); fma2(acc[3][0], d, uu0.x); fma2(acc[3][1], d, uu0.y);
                d = dupf(hv0.y); fma2(acc[0][0], d, uu1.x); fma2(acc[0][1], d, uu1.y);
                d = dupf(hv1.y); fma2(acc[1][0], d, uu1.x); fma2(acc[1][1], d, uu1.y);
                d = dupf(hv2.y); fma2(acc[2][0], d, uu1.x); fma2(acc[2][1], d, uu1.y);
                d = dupf(hv3.y); fma2(acc[3][0], d, uu1.x); fma2(acc[3][1], d, uu1.y);
                d = dupf(hv0.z); fma2(acc[0][0], d, uu2.x); fma2(acc[0][1], d, uu2.y);
                d = dupf(hv1.z); fma2(acc[1][0], d, uu2.x); fma2(acc[1][1], d, uu2.y);
                d = dupf(hv2.z); fma2(acc[2][0], d, uu2.x); fma2(acc[2][1], d, uu2.y);
                d = dupf(hv3.z); fma2(acc[3][0], d, uu2.x); fma2(acc[3][1], d, uu2.y);
                d = dupf(hv0.w); fma2(acc[0][0], d, uu3.x); fma2(acc[0][1], d, uu3.y);
                d = dupf(hv1.w); fma2(acc[1][0], d, uu3.x); fma2(acc[1][1], d, uu3.y);
                d = dupf(hv2.w); fma2(acc[2][0], d, uu3.x); fma2(acc[2][1], d, uu3.y);
                d = dupf(hv3.w); fma2(acc[3][0], d, uu3.x); fma2(acc[3][1], d, uu3.y);
            }
            int rbase = w * 256;
#pragma unroll
            for (int i = 0; i < 4; i++) {
                int bl = bg * 4 + i;
                red[rbase + bl * 16 + ((ng * 2)     ^ (bg << 1))] = acc[i][0];
                red[rbase + bl * 16 + ((ng * 2 + 1) ^ (bg << 1))] = acc[i][1];
            }
            __syncthreads();
            {
                u64 ssum = red[o1c];
#pragma unroll
                for (int p = 1; p < 8; p++) ssum = add2(ssum, red[p * 256 + o1c]);
                float v0s, v1s; unpk(ssum, v0s, v1s);
                float a0 = pre1.x + v0s + ub1.x;
                float a1 = pre1.y + v1s + ub1.y;
                float v0 = 1.f / (1.f + __expf(-a0));
                float v1 = 1.f / (1.f + __expf(-a1));
                if (cl < 16) {
                    *(float2*)&g_z[b1 * 512 + n1] = make_float2(v0, v1);
                } else {
                    int j = n1 - 512;
                    int c = j >> 2;
                    const float* ch = (const float*)&hs4[b1l * 128 + swz2(b1l, c)];
                    *(float2*)&g_rh[b1 * 512 + j] =
                        make_float2(v0 * ch[j & 3], v1 * ch[(j & 3) + 1]);
                }
            }
        }
        group_sync(gbase, ++bar);

        // --- prefetch z for P2 epilogue ---
        float2 zf = make_float2(0.f, 0.f);
        if (tid < 128) zf = *(const float2*)&g_z[b2 * 512 + n2];

        // --- warp-private load of rh tile chunks [w*16, w*16+16) ---
        {
            const float4* rp4 = (const float4*)(g_rh + gb0 * 512);
#pragma unroll
            for (int q = 0; q < 8; q++) {
                int r = q * 2 + rh2;
                rs4[r * 128 + swz2(r, cch)] = rp4[r * 128 + cch];
            }
            __syncwarp();
        }

        // ================= Phase 2: h~ = tanh(pre + rh@Uh^T + ub) ===========
        {
            u64 acc[2][2];
            acc[0][0] = acc[0][1] = acc[1][0] = acc[1][1] = 0ull;
            const float4* rr0 = rs4 + (bg2 * 2 + 0) * 128;
            const float4* rr1 = rs4 + (bg2 * 2 + 1) * 128;
            const int q0 = bg2, q1 = bg2 ^ 4;
            const float* upc = u2 + ng2 * 4;
#pragma unroll
            for (int cc = 0; cc < 16; cc++) {
                int cb = w * 16 + cc;
                int cx = cb ^ w;
                float4 rv0 = rr0[cx ^ q0];
                float4 rv1 = rr1[cx ^ q1];
                const float* ub = upc + cb * 64;
                ulonglong2 uu0 = *(const ulonglong2*)(ub);
                ulonglong2 uu1 = *(const ulonglong2*)(ub + 16);
                ulonglong2 uu2 = *(const ulonglong2*)(ub + 32);
                ulonglong2 uu3 = *(const ulonglong2*)(ub + 48);
                u64 d;
                d = dupf(rv0.x); fma2(acc[0][0], d, uu0.x); fma2(acc[0][1], d, uu0.y);
                d = dupf(rv1.x); fma2(acc[1][0], d, uu0.x); fma2(acc[1][1], d, uu0.y);
                d = dupf(rv0.y); fma2(acc[0][0], d, uu1.x); fma2(acc[0][1], d, uu1.y);
                d = dupf(rv1.y); fma2(acc[1][0], d, uu1.x); fma2(acc[1][1], d, uu1.y);
                d = dupf(rv0.z); fma2(acc[0][0], d, uu2.x); fma2(acc[0][1], d, uu2.y);
                d = dupf(rv1.z); fma2(acc[1][0], d, uu2.x); fma2(acc[1][1], d, uu2.y);
                d = dupf(rv0.w); fma2(acc[0][0], d, uu3.x); fma2(acc[0][1], d, uu3.y);
                d = dupf(rv1.w); fma2(acc[1][0], d, uu3.x); fma2(acc[1][1], d, uu3.y);
            }
            int rbase = w * 128;
#pragma unroll
            for (int i = 0; i < 2; i++) {
                int bl = bg2 * 2 + i;
                red[rbase + bl * 8 + ((ng2 * 2)     ^ (bg2 & 3))] = acc[i][0];
                red[rbase + bl * 8 + ((ng2 * 2 + 1) ^ (bg2 & 3))] = acc[i][1];
            }
            __syncthreads();
            if (tid < 128) {
                u64 ssum = red[o2c];
#pragma unroll
                for (int p = 1; p < 8; p++) ssum = add2(ssum, red[p * 128 + o2c]);
                float v0s, v1s; unpk(ssum, v0s, v1s);
                int c = n2 >> 2;
                const float* ch = (const float*)&hs4[b2l * 128 + swz2(b2l, c)];
                float hp0 = ch[n2 & 3], hp1 = ch[(n2 & 3) + 1];
                float a0 = pre2.x + v0s + ub2.x;
                float a1 = pre2.y + v1s + ub2.y;
                float e0 = __expf(2.f * a0), e1 = __expf(2.f * a1);
                float th0 = 1.f - 2.f / (e0 + 1.f);
                float th1 = 1.f - 2.f / (e1 + 1.f);
                float hn0 = hp0 + zf.x * (th0 - hp0);
                float hn1 = hp1 + zf.y * (th1 - hp1);
                float2 o = make_float2(hn0, hn1);
                *(float2*)&out[s * (B_DIM * 512) + b2 * 512 + n2] = o;
                if (s == S_LEN - 1)
                    *(float2*)&out[S_LEN * (B_DIM * 512) + b2 * 512 + n2] = o;
            }
        }

        // ===== end-of-step barrier with next-step prefetch in its shadow ====
        __syncthreads();                    // out stores + hs4/rs4 reads done
        ++bar;
        if (tid == 0) {
            asm volatile("st.release.gpu.u32 [%0], %1;"
                         :: "l"(&g_flags[cta * 32]), "r"(bar) : "memory");
        }
        {
            int sp = (s + 1 < S_LEN) ? (s + 1) : s;   // clamp for last step
            pre1 = *(const float2*)&g_pre[(sp * 64 + b1) * 1536 + n1];
            if (tid < 128)
                pre2 = *(const float2*)&g_pre[(sp * 64 + b2) * 1536 + 1024 + n2];
        }
        if (tid < GRP_CTAS) {
            unsigned v;
            const unsigned* fp = &g_flags[(gbase + tid) * 32];
            do {
                asm volatile("ld.acquire.gpu.u32 %0, [%1];"
                             : "=r"(v) : "l"(fp) : "memory");
            } while (v < bar);
        }
        __syncthreads();
    }
}

// ---------------- launch ----------------------------------------------------
extern "C" void kernel_launch(void* const* d_in, const int* in_sizes, int n_in,
                              void* d_out, int out_size) {
    (void)in_sizes; (void)n_in; (void)out_size;
    const float* x    = (const float*)d_in[0];
    const float* h0   = (const float*)d_in[1];
    const float* Wz_w = (const float*)d_in[2];
    const float* Wz_b = (const float*)d_in[3];
    const float* Uz_w = (const float*)d_in[4];
    const float* Uz_b = (const float*)d_in[5];
    const float* Wr_w = (const float*)d_in[6];
    const float* Wr_b = (const float*)d_in[7];
    const float* Ur_w = (const float*)d_in[8];
    const float* Ur_b = (const float*)d_in[9];
    const float* Wh_w = (const float*)d_in[10];
    const float* Wh_b = (const float*)d_in[11];
    const float* Uh_w = (const float*)d_in[12];
    const float* Uh_b = (const float*)d_in[13];
    float* out = (float*)d_out;

    static int smem_set = 0;
    if (!smem_set) {
        cudaFuncSetAttribute(gru_scan, cudaFuncAttributeMaxDynamicSharedMemorySize,
                             180224);
        smem_set = 1;
    }

    pack_kernel<<<256, 256>>>(Wz_w, Wz_b, Uz_w, Uz_b,
                              Wr_w, Wr_b, Ur_w, Ur_b,
                              Wh_w, Wh_b, Uh_w, Uh_b);
    input_gemm<<<dim3(24, 512), 256>>>(x);
    gru_scan<<<NBLK, 256, 180224>>>(h0, out);
}

// round 11
// speedup vs baseline: 1.8722x; 1.0837x over previous
#include <cuda_runtime.h>
#include <math.h>

#define S_LEN 1024
#define B_DIM 64
#define NBLK  128
#define GRP_CTAS 32

typedef unsigned long long u64;

// ---------------- f32x2 helpers (sm_100+) -----------------------------------
__device__ __forceinline__ u64 dupf(float x) {
    u64 r; unsigned xi = __float_as_uint(x);
    asm("mov.b64 %0, {%1, %1};" : "=l"(r) : "r"(xi));
    return r;
}
__device__ __forceinline__ void fma2(u64& d, u64 a, u64 b) {
    asm("fma.rn.f32x2 %0, %1, %2, %0;" : "+l"(d) : "l"(a), "l"(b));
}
__device__ __forceinline__ u64 add2(u64 a, u64 b) {
    u64 d; asm("add.rn.f32x2 %0, %1, %2;" : "=l"(d) : "l"(a), "l"(b));
    return d;
}
__device__ __forceinline__ void unpk(u64 p, float& lo, float& hi) {
    unsigned a, b;
    asm("mov.b64 {%0, %1}, %2;" : "=r"(a), "=r"(b) : "l"(p));
    lo = __uint_as_float(a); hi = __uint_as_float(b);
}

// swizzled chunk column for 16-row tiles
__device__ __forceinline__ int swz2(int b, int c) {
    return c ^ ((b >> 1) & 7) ^ ((c >> 4) & 7) ^ ((b & 1) << 2);
}

// ---------------- device scratch --------------------------------------------
__device__ float g_pre[S_LEN * B_DIM * 1536];   // xz|xr|xh preactivations
__device__ float g_WT[512 * 1536];              // [k][n] input weights (k-major)
__device__ float g_Uzrp[32 * 512 * 32];         // packed [cl][k][32n] zr weights
__device__ float g_Uhp[32 * 512 * 16];          // packed [cl][k][16n] h weights
__device__ float g_wbias[1536];
__device__ float g_ubias[1536];
__device__ float g_z[2][B_DIM * 512];           // parity-buffered gate values
__device__ float g_rh[2][B_DIM * 512];
__device__ unsigned g_flags[NBLK * 32];         // per-CTA flags, 128B stride

// ---------------- pack + flag reset -----------------------------------------
__global__ void pack_kernel(const float* Wz, const float* bz, const float* Uz, const float* ubz,
                            const float* Wr, const float* br, const float* Ur, const float* ubr,
                            const float* Wh, const float* bh, const float* Uh, const float* ubh) {
    int stride = gridDim.x * blockDim.x;
    int t = blockIdx.x * blockDim.x + threadIdx.x;
    for (int idx = t; idx < NBLK * 32; idx += stride) g_flags[idx] = 0u;
    for (int idx = t; idx < 512 * 1536; idx += stride) {
        int k = idx / 1536, n = idx % 1536;
        const float* W = (n < 512) ? Wz : (n < 1024 ? Wr : Wh);
        g_WT[idx] = W[(n & 511) * 512 + k];
    }
    for (int idx = t; idx < 32 * 512 * 32; idx += stride) {
        int cl = idx >> 14, k = (idx >> 5) & 511, nn = idx & 31;
        int n = cl * 32 + nn;
        g_Uzrp[idx] = (n < 512) ? Uz[n * 512 + k] : Ur[(n - 512) * 512 + k];
    }
    for (int idx = t; idx < 32 * 512 * 16; idx += stride) {
        int cl = idx >> 13, k = (idx >> 4) & 511, nn = idx & 15;
        g_Uhp[idx] = Uh[(cl * 16 + nn) * 512 + k];
    }
    for (int idx = t; idx < 1536; idx += stride) {
        int n = idx & 511;
        g_wbias[idx] = (idx < 512) ? bz[n] : (idx < 1024 ? br[n] : bh[n]);
        g_ubias[idx] = (idx < 512) ? ubz[n] : (idx < 1024 ? ubr[n] : ubh[n]);
    }
}

// ---------------- input projection GEMM (f32x2, double-buffered) ------------
__global__ __launch_bounds__(256) void input_gemm(const float* __restrict__ x) {
    __shared__ float As[2][16 * 132];
    __shared__ float Bs[2][16 * 64];
    int tid = threadIdx.x;
    int tx = tid & 15, ty = tid >> 4;
    int m0 = blockIdx.y * 128;
    int n0 = blockIdx.x * 64;

    const int fA0 = tid,       mA0 = fA0 >> 2, kqA0 = fA0 & 3;
    const int fA1 = 256 + tid, mA1 = fA1 >> 2, kqA1 = fA1 & 3;
    const int kB  = tid >> 4,  nqB = tid & 15;
    const float* xA0 = x + (m0 + mA0) * 512 + kqA0 * 4;
    const float* xA1 = x + (m0 + mA1) * 512 + kqA1 * 4;
    const float* wB  = g_WT + kB * 1536 + n0 + nqB * 4;

    u64 acc[8][2];
#pragma unroll
    for (int i = 0; i < 8; i++) { acc[i][0] = 0ull; acc[i][1] = 0ull; }

    {
        float4 a0 = *(const float4*)(xA0);
        float4 a1 = *(const float4*)(xA1);
        float4 b0 = *(const float4*)(wB);
        As[0][(kqA0 * 4 + 0) * 132 + mA0] = a0.x;
        As[0][(kqA0 * 4 + 1) * 132 + mA0] = a0.y;
        As[0][(kqA0 * 4 + 2) * 132 + mA0] = a0.z;
        As[0][(kqA0 * 4 + 3) * 132 + mA0] = a0.w;
        As[0][(kqA1 * 4 + 0) * 132 + mA1] = a1.x;
        As[0][(kqA1 * 4 + 1) * 132 + mA1] = a1.y;
        As[0][(kqA1 * 4 + 2) * 132 + mA1] = a1.z;
        As[0][(kqA1 * 4 + 3) * 132 + mA1] = a1.w;
        *(float4*)&Bs[0][kB * 64 + nqB * 4] = b0;
    }
    __syncthreads();

    for (int kt = 0; kt < 32; kt++) {
        int cur = kt & 1;
        float4 a0n, a1n, b0n;
        if (kt < 31) {
            int k0 = (kt + 1) * 16;
            a0n = *(const float4*)(xA0 + k0);
            a1n = *(const float4*)(xA1 + k0);
            b0n = *(const float4*)(wB + (unsigned)k0 * 1536);
        }
        const float* Ac = As[cur];
        const float* Bc = Bs[cur];
#pragma unroll
        for (int kk = 0; kk < 16; kk++) {
            float4 a0 = *(const float4*)&Ac[kk * 132 + ty * 8];
            float4 a1 = *(const float4*)&Ac[kk * 132 + ty * 8 + 4];
            ulonglong2 bb = *(const ulonglong2*)&Bc[kk * 64 + tx * 4];
            u64 d0 = dupf(a0.x), d1 = dupf(a0.y), d2 = dupf(a0.z), d3 = dupf(a0.w);
            u64 d4 = dupf(a1.x), d5 = dupf(a1.y), d6 = dupf(a1.z), d7 = dupf(a1.w);
            fma2(acc[0][0], d0, bb.x); fma2(acc[0][1], d0, bb.y);
            fma2(acc[1][0], d1, bb.x); fma2(acc[1][1], d1, bb.y);
            fma2(acc[2][0], d2, bb.x); fma2(acc[2][1], d2, bb.y);
            fma2(acc[3][0], d3, bb.x); fma2(acc[3][1], d3, bb.y);
            fma2(acc[4][0], d4, bb.x); fma2(acc[4][1], d4, bb.y);
            fma2(acc[5][0], d5, bb.x); fma2(acc[5][1], d5, bb.y);
            fma2(acc[6][0], d6, bb.x); fma2(acc[6][1], d6, bb.y);
            fma2(acc[7][0], d7, bb.x); fma2(acc[7][1], d7, bb.y);
        }
        if (kt < 31) {
            int nxt = cur ^ 1;
            As[nxt][(kqA0 * 4 + 0) * 132 + mA0] = a0n.x;
            As[nxt][(kqA0 * 4 + 1) * 132 + mA0] = a0n.y;
            As[nxt][(kqA0 * 4 + 2) * 132 + mA0] = a0n.z;
            As[nxt][(kqA0 * 4 + 3) * 132 + mA0] = a0n.w;
            As[nxt][(kqA1 * 4 + 0) * 132 + mA1] = a1n.x;
            As[nxt][(kqA1 * 4 + 1) * 132 + mA1] = a1n.y;
            As[nxt][(kqA1 * 4 + 2) * 132 + mA1] = a1n.z;
            As[nxt][(kqA1 * 4 + 3) * 132 + mA1] = a1n.w;
            *(float4*)&Bs[nxt][kB * 64 + nqB * 4] = b0n;
            __syncthreads();
        }
    }
#pragma unroll
    for (int i = 0; i < 8; i++) {
        int m = m0 + ty * 8 + i;
        int n = n0 + tx * 4;
        float4 o;
        float v0, v1, v2, v3;
        unpk(acc[i][0], v0, v1);
        unpk(acc[i][1], v2, v3);
        o.x = v0 + g_wbias[n + 0];
        o.y = v1 + g_wbias[n + 1];
        o.z = v2 + g_wbias[n + 2];
        o.w = v3 + g_wbias[n + 3];
        *(float4*)&g_pre[m * 1536 + n] = o;
    }
}

// ---------------- persistent GRU scan: fine-grained producer waits ----------
// 4 groups x 32 CTAs; group g owns batch rows [g*16, g*16+16).
// Flags: one monotone counter per CTA: 2s+1 = z/rh written, 2s+2 = out written.
// Warp w waits only on its data producers (4 for h, 2+1 for rh/z); full
// fan-in resolves at the reduce __syncthreads. g_rh/g_z parity-buffered:
// reuse at s+2 is safe because P1-reduce sync at step t implies ALL group
// flags >= 2t (8 warps jointly cover all 32 producers).
__global__ __launch_bounds__(256, 1) void gru_scan(const float* __restrict__ h0,
                                                   float* out) {
    extern __shared__ float smem[];
    float4* hs4 = (float4*)smem;                // [16][128] chunks swizzled, 32KB
    float4* rs4 = hs4 + 2048;                   // [16][128] chunks swizzled, 32KB
    float*  us  = smem + 16384;                 // [512][32]  64KB zr weights
    float*  u2  = smem + 32768;                 // [512][16]  32KB h  weights
    u64*    red = (u64*)(smem + 40960);         // 2048 u64   16KB

    const int tid  = threadIdx.x;
    const int cta  = blockIdx.x;
    const int w    = tid >> 5;
    const int lane = tid & 31;
    const int g    = cta >> 5;
    const int cl   = cta & 31;
    const int gbase = cta & ~(GRP_CTAS - 1);
    const int gb0  = g * 16;                    // group batch base

    // --- resident weights ---
    {
        const float* up1 = g_Uzrp + cl * 16384;
#pragma unroll
        for (int i = 0; i < 16; i++) {
            int off = (i * 256 + tid) * 4;
            *(float4*)&us[off] = *(const float4*)(up1 + off);
        }
        const float* up2 = g_Uhp + cl * 8192;
#pragma unroll
        for (int i = 0; i < 8; i++) {
            int off = (i * 256 + tid) * 4;
            *(float4*)&u2[off] = *(const float4*)(up2 + off);
        }
    }

    // --- epilogue constants ---
    const int b1l = tid >> 4;                  // P1 local b (0..15)
    const int b1  = gb0 + b1l;
    const int n1  = cl * 32 + (tid & 15) * 2;  // P1 n (0..1022)
    const float2 ub1 = *(const float2*)&g_ubias[n1];
    const int o1c = b1l * 16 + ((tid & 15) ^ ((b1l >> 2) << 1));
    const int o2  = tid & 127;
    const int b2l = o2 >> 3;
    const int b2  = gb0 + b2l;
    const int n2  = cl * 16 + (o2 & 7) * 2;
    const float2 ub2 = *(const float2*)&g_ubias[1024 + n2];
    const int o2c = b2l * 8 + ((o2 & 7) ^ ((b2l >> 1) & 3));

    // --- compute-lane constants ---
    const int bg  = lane >> 3;   // P1: 4 b-groups of 4 rows
    const int ng  = lane & 7;    // P1: 8 n-groups of 4 cols
    const int bg2 = lane >> 2;   // P2: 8 b-groups of 2 rows
    const int ng2 = lane & 3;    // P2: 4 n-groups of 4 cols
    // warp-private tile-load lane map: r = q*2 + rh2, c = w*16 + wl
    const int wl  = lane & 15;
    const int rh2 = lane >> 4;
    const int cch = w * 16 + wl;

    // --- producer sets for this warp / CTA ---
    const int hprod  = gbase + w * 4;          // h producers: +0..+3
    const int rprod  = gbase + 16 + w * 2;     // rh producers: +0..+1
    const int zprod  = gbase + (cl >> 1);      // z producer for this CTA's slice

    // --- prefetch step-0 epilogue operands ---
    float2 pre1 = *(const float2*)&g_pre[b1 * 1536 + n1];
    float2 pre2 = make_float2(0.f, 0.f);
    if (tid < 128)
        pre2 = *(const float2*)&g_pre[b2 * 1536 + 1024 + n2];

    for (int s = 0; s < S_LEN; s++) {
        const float* hprev = (s == 0) ? h0 : (out + (s - 1) * (B_DIM * 512));
        const int par = s & 1;

        // ===== per-warp wait: my 4 h-producers wrote out[s-1] (>= 2s) =====
        {
            unsigned tgt = (unsigned)(2 * s);
            if (lane < 4) {
                const unsigned* fp = &g_flags[(hprod + lane) * 32];
                unsigned v;
                do {
                    asm volatile("ld.acquire.gpu.u32 %0, [%1];"
                                 : "=r"(v) : "l"(fp) : "memory");
                } while (v < tgt);
            }
            __syncwarp();
        }

        // --- warp-private load of h tile chunks [w*16, w*16+16) ---
        {
            const float4* hp4 = (const float4*)(hprev + gb0 * 512);
#pragma unroll
            for (int q = 0; q < 8; q++) {
                int r = q * 2 + rh2;
                hs4[r * 128 + swz2(r, cch)] = hp4[r * 128 + cch];
            }
            __syncwarp();
        }

        // ================= Phase 1: zr = sigmoid(pre + h@Uzr^T + ub) ========
        {
            u64 acc[4][2];
#pragma unroll
            for (int i = 0; i < 4; i++) { acc[i][0] = 0ull; acc[i][1] = 0ull; }
            const float4* hr0 = hs4 + (bg * 4 + 0) * 128;
            const float4* hr1 = hs4 + (bg * 4 + 1) * 128;
            const float4* hr2 = hs4 + (bg * 4 + 2) * 128;
            const float4* hr3 = hs4 + (bg * 4 + 3) * 128;
            const int m0 = bg * 2, m1 = (bg * 2) ^ 4;
            const int m2 = bg * 2 + 1, m3 = (bg * 2 + 1) ^ 4;
            const float* upc = us + ng * 4;
#pragma unroll
            for (int cc = 0; cc < 16; cc++) {
                int cb = w * 16 + cc;
                int cx = cb ^ w;
                float4 hv0 = hr0[cx ^ m0];
                float4 hv1 = hr1[cx ^ m1];
                float4 hv2 = hr2[cx ^ m2];
                float4 hv3 = hr3[cx ^ m3];
                const float* ub = upc + cb * 128;
                ulonglong2 uu0 = *(const ulonglong2*)(ub);
                ulonglong2 uu1 = *(const ulonglong2*)(ub + 32);
                ulonglong2 uu2 = *(const ulonglong2*)(ub + 64);
                ulonglong2 uu3 = *(const ulonglong2*)(ub + 96);
                u64 d;
                d = dupf(hv0.x); fma2(acc[0][0], d, uu0.x); fma2(acc[0][1], d, uu0.y);
                d = dupf(hv1.x); fma2(acc[1][0], d, uu0.x); fma2(acc[1][1], d, uu0.y);
                d = dupf(hv2.x); fma2(acc[2][0], d, uu0.x); fma2(acc[2][1], d, uu0.y);
                d = dupf(hv3.x); fma2(acc[3][0], d, uu0.x); fma2(acc[3][1], d, uu0.y);
                d = dupf(hv0.y); fma2(acc[0][0], d, uu1.x); fma2(acc[0][1], d, uu1.y);
                d = dupf(hv1.y); fma2(acc[1][0], d, uu1.x); fma2(acc[1][1], d, uu1.y);
                d = dupf(hv2.y); fma2(acc[2][0], d, uu1.x); fma2(acc[2][1], d, uu1.y);
                d = dupf(hv3.y); fma2(acc[3][0], d, uu1.x); fma2(acc[3][1], d, uu1.y);
                d = dupf(hv0.z); fma2(acc[0][0], d, uu2.x); fma2(acc[0][1], d, uu2.y);
                d = dupf(hv1.z); fma2(acc[1][0], d, uu2.x); fma2(acc[1][1], d, uu2.y);
                d = dupf(hv2.z); fma2(acc[2][0], d, uu2.x); fma2(acc[2][1], d, uu2.y);
                d = dupf(hv3.z); fma2(acc[3][0], d, uu2.x); fma2(acc[3][1], d, uu2.y);
                d = dupf(hv0.w); fma2(acc[0][0], d, uu3.x); fma2(acc[0][1], d, uu3.y);
                d = dupf(hv1.w); fma2(acc[1][0], d, uu3.x); fma2(acc[1][1], d, uu3.y);
                d = dupf(hv2.w); fma2(acc[2][0], d, uu3.x); fma2(acc[2][1], d, uu3.y);
                d = dupf(hv3.w); fma2(acc[3][0], d, uu3.x); fma2(acc[3][1], d, uu3.y);
            }
            int rbase = w * 256;
#pragma unroll
            for (int i = 0; i < 4; i++) {
                int bl = bg * 4 + i;
                red[rbase + bl * 16 + ((ng * 2)     ^ (bg << 1))] = acc[i][0];
                red[rbase + bl * 16 + ((ng * 2 + 1) ^ (bg << 1))] = acc[i][1];
            }
            __syncthreads();   // NOTE: implies all 32 group flags >= 2s
            {
                u64 ssum = red[o1c];
#pragma unroll
                for (int p = 1; p < 8; p++) ssum = add2(ssum, red[p * 256 + o1c]);
                float v0s, v1s; unpk(ssum, v0s, v1s);
                float a0 = pre1.x + v0s + ub1.x;
                float a1 = pre1.y + v1s + ub1.y;
                float v0 = 1.f / (1.f + __expf(-a0));
                float v1 = 1.f / (1.f + __expf(-a1));
                if (cl < 16) {
                    *(float2*)&g_z[par][b1 * 512 + n1] = make_float2(v0, v1);
                } else {
                    int j = n1 - 512;
                    int c = j >> 2;
                    const float* ch = (const float*)&hs4[b1l * 128 + swz2(b1l, c)];
                    *(float2*)&g_rh[par][b1 * 512 + j] =
                        make_float2(v0 * ch[j & 3], v1 * ch[(j & 3) + 1]);
                }
            }
        }
        __syncthreads();       // all z/rh stores done
        if (tid == 0) {
            asm volatile("st.release.gpu.u32 [%0], %1;"
                         :: "l"(&g_flags[cta * 32]), "r"((unsigned)(2 * s + 1)) : "memory");
        }

        // ===== per-warp wait: my 2 rh-producers + z-producer (>= 2s+1) =====
        {
            unsigned tgt = (unsigned)(2 * s + 1);
            if (lane < 3) {
                int p = (lane < 2) ? (rprod + lane) : zprod;
                const unsigned* fp = &g_flags[p * 32];
                unsigned v;
                do {
                    asm volatile("ld.acquire.gpu.u32 %0, [%1];"
                                 : "=r"(v) : "l"(fp) : "memory");
                } while (v < tgt);
            }
            __syncwarp();
        }

        // --- prefetch z for P2 epilogue (producer flag verified above) ---
        float2 zf = make_float2(0.f, 0.f);
        if (tid < 128) zf = *(const float2*)&g_z[par][b2 * 512 + n2];

        // --- warp-private load of rh tile chunks [w*16, w*16+16) ---
        {
            const float4* rp4 = (const float4*)(g_rh[par] + gb0 * 512);
#pragma unroll
            for (int q = 0; q < 8; q++) {
                int r = q * 2 + rh2;
                rs4[r * 128 + swz2(r, cch)] = rp4[r * 128 + cch];
            }
            __syncwarp();
        }

        // ================= Phase 2: h~ = tanh(pre + rh@Uh^T + ub) ===========
        {
            u64 acc[2][2];
            acc[0][0] = acc[0][1] = acc[1][0] = acc[1][1] = 0ull;
            const float4* rr0 = rs4 + (bg2 * 2 + 0) * 128;
            const float4* rr1 = rs4 + (bg2 * 2 + 1) * 128;
            const int q0 = bg2, q1 = bg2 ^ 4;
            const float* upc = u2 + ng2 * 4;
#pragma unroll
            for (int cc = 0; cc < 16; cc++) {
                int cb = w * 16 + cc;
                int cx = cb ^ w;
                float4 rv0 = rr0[cx ^ q0];
                float4 rv1 = rr1[cx ^ q1];
                const float* ub = upc + cb * 64;
                ulonglong2 uu0 = *(const ulonglong2*)(ub);
                ulonglong2 uu1 = *(const ulonglong2*)(ub + 16);
                ulonglong2 uu2 = *(const ulonglong2*)(ub + 32);
                ulonglong2 uu3 = *(const ulonglong2*)(ub + 48);
                u64 d;
                d = dupf(rv0.x); fma2(acc[0][0], d, uu0.x); fma2(acc[0][1], d, uu0.y);
                d = dupf(rv1.x); fma2(acc[1][0], d, uu0.x); fma2(acc[1][1], d, uu0.y);
                d = dupf(rv0.y); fma2(acc[0][0], d, uu1.x); fma2(acc[0][1], d, uu1.y);
                d = dupf(rv1.y); fma2(acc[1][0], d, uu1.x); fma2(acc[1][1], d, uu1.y);
                d = dupf(rv0.z); fma2(acc[0][0], d, uu2.x); fma2(acc[0][1], d, uu2.y);
                d = dupf(rv1.z); fma2(acc[1][0], d, uu2.x); fma2(acc[1][1], d, uu2.y);
                d = dupf(rv0.w); fma2(acc[0][0], d, uu3.x); fma2(acc[0][1], d, uu3.y);
                d = dupf(rv1.w); fma2(acc[1][0], d, uu3.x); fma2(acc[1][1], d, uu3.y);
            }
            int rbase = w * 128;
#pragma unroll
            for (int i = 0; i < 2; i++) {
                int bl = bg2 * 2 + i;
                red[rbase + bl * 8 + ((ng2 * 2)     ^ (bg2 & 3))] = acc[i][0];
                red[rbase + bl * 8 + ((ng2 * 2 + 1) ^ (bg2 & 3))] = acc[i][1];
            }
            __syncthreads();
            if (tid < 128) {
                u64 ssum = red[o2c];
#pragma unroll
                for (int p = 1; p < 8; p++) ssum = add2(ssum, red[p * 128 + o2c]);
                float v0s, v1s; unpk(ssum, v0s, v1s);
                int c = n2 >> 2;
                const float* ch = (const float*)&hs4[b2l * 128 + swz2(b2l, c)];
                float hp0 = ch[n2 & 3], hp1 = ch[(n2 & 3) + 1];
                float a0 = pre2.x + v0s + ub2.x;
                float a1 = pre2.y + v1s + ub2.y;
                float e0 = __expf(2.f * a0), e1 = __expf(2.f * a1);
                float th0 = 1.f - 2.f / (e0 + 1.f);
                float th1 = 1.f - 2.f / (e1 + 1.f);
                float hn0 = hp0 + zf.x * (th0 - hp0);
                float hn1 = hp1 + zf.y * (th1 - hp1);
                float2 o = make_float2(hn0, hn1);
                *(float2*)&out[s * (B_DIM * 512) + b2 * 512 + n2] = o;
                if (s == S_LEN - 1)
                    *(float2*)&out[S_LEN * (B_DIM * 512) + b2 * 512 + n2] = o;
            }
        }
        __syncthreads();       // out stores + hs4/rs4 epilogue reads done
        if (tid == 0) {
            asm volatile("st.release.gpu.u32 [%0], %1;"
                         :: "l"(&g_flags[cta * 32]), "r"((unsigned)(2 * s + 2)) : "memory");
        }
        // next-step epilogue prefetch in the release/wait shadow
        {
            int sp = (s + 1 < S_LEN) ? (s + 1) : s;
            pre1 = *(const float2*)&g_pre[(sp * 64 + b1) * 1536 + n1];
            if (tid < 128)
                pre2 = *(const float2*)&g_pre[(sp * 64 + b2) * 1536 + 1024 + n2];
        }
    }
}

// ---------------- launch ----------------------------------------------------
extern "C" void kernel_launch(void* const* d_in, const int* in_sizes, int n_in,
                              void* d_out, int out_size) {
    (void)in_sizes; (void)n_in; (void)out_size;
    const float* x    = (const float*)d_in[0];
    const float* h0   = (const float*)d_in[1];
    const float* Wz_w = (const float*)d_in[2];
    const float* Wz_b = (const float*)d_in[3];
    const float* Uz_w = (const float*)d_in[4];
    const float* Uz_b = (const float*)d_in[5];
    const float* Wr_w = (const float*)d_in[6];
    const float* Wr_b = (const float*)d_in[7];
    const float* Ur_w = (const float*)d_in[8];
    const float* Ur_b = (const float*)d_in[9];
    const float* Wh_w = (const float*)d_in[10];
    const float* Wh_b = (const float*)d_in[11];
    const float* Uh_w = (const float*)d_in[12];
    const float* Uh_b = (const float*)d_in[13];
    float* out = (float*)d_out;

    static int smem_set = 0;
    if (!smem_set) {
        cudaFuncSetAttribute(gru_scan, cudaFuncAttributeMaxDynamicSharedMemorySize,
                             180224);
        smem_set = 1;
    }

    pack_kernel<<<256, 256>>>(Wz_w, Wz_b, Uz_w, Uz_b,
                              Wr_w, Wr_b, Ur_w, Ur_b,
                              Wh_w, Wh_b, Uh_w, Uh_b);
    input_gemm<<<dim3(24, 512), 256>>>(x);
    gru_scan<<<NBLK, 256, 180224>>>(h0, out);
}